// round 3
// baseline (speedup 1.0000x reference)
#include <cuda_runtime.h>
#include <cuda_bf16.h>
#include <math.h>

#define SEQ 2048
#define EMB 1024
#define NH  16
#define HD  64

// Scratch (device globals — no allocation allowed)
__device__ __nv_bfloat16 g_Q[NH * SEQ * HD];
__device__ __nv_bfloat16 g_K[NH * SEQ * HD];
__device__ __nv_bfloat16 g_V[NH * SEQ * HD];
__device__ __nv_bfloat16 g_S[(size_t)NH * SEQ * SEQ];   // masked bf16 scores
__device__ float g_attn[SEQ * EMB];

__device__ __forceinline__ float bf16r(float v) {
    return __bfloat162float(__float2bfloat16(v));
}

// ---------------------------------------------------------------------------
// Fused QKV projection: P = x @ W + b, cast bf16, scatter into [H,S,D] layout.
// 128x128x8 register-blocked SGEMM, 256 threads, 8x8 micro-tile.
// ---------------------------------------------------------------------------
__global__ __launch_bounds__(256) void proj_qkv_kernel(
    const float* __restrict__ x,
    const float* __restrict__ Wq, const float* __restrict__ bq,
    const float* __restrict__ Wk, const float* __restrict__ bk,
    const float* __restrict__ Wv, const float* __restrict__ bv)
{
    const float* W; const float* bias; __nv_bfloat16* out;
    if (blockIdx.z == 0)      { W = Wq; bias = bq; out = g_Q; }
    else if (blockIdx.z == 1) { W = Wk; bias = bk; out = g_K; }
    else                      { W = Wv; bias = bv; out = g_V; }

    __shared__ float As[8][128];
    __shared__ float Bs[8][128];
    const int tid = threadIdx.x;
    const int tx = tid & 15, ty = tid >> 4;
    const int bM = blockIdx.y * 128, bN = blockIdx.x * 128;

    float acc[8][8] = {};

    for (int k0 = 0; k0 < EMB; k0 += 8) {
        {
            int ar = tid >> 1, ac = (tid & 1) * 4;
            float4 av = *(const float4*)(x + (size_t)(bM + ar) * EMB + k0 + ac);
            As[ac + 0][ar] = av.x; As[ac + 1][ar] = av.y;
            As[ac + 2][ar] = av.z; As[ac + 3][ar] = av.w;
        }
        {
            int br = tid >> 5, bc = (tid & 31) * 4;
            *(float4*)&Bs[br][bc] =
                *(const float4*)(W + (size_t)(k0 + br) * EMB + bN + bc);
        }
        __syncthreads();
        #pragma unroll
        for (int kk = 0; kk < 8; kk++) {
            float a[8], b[8];
            *(float4*)&a[0] = *(float4*)&As[kk][ty * 8];
            *(float4*)&a[4] = *(float4*)&As[kk][ty * 8 + 4];
            *(float4*)&b[0] = *(float4*)&Bs[kk][tx * 8];
            *(float4*)&b[4] = *(float4*)&Bs[kk][tx * 8 + 4];
            #pragma unroll
            for (int i = 0; i < 8; i++)
                #pragma unroll
                for (int j = 0; j < 8; j++)
                    acc[i][j] = fmaf(a[i], b[j], acc[i][j]);
        }
        __syncthreads();
    }

    #pragma unroll
    for (int i = 0; i < 8; i++) {
        int m = bM + ty * 8 + i;
        #pragma unroll
        for (int j = 0; j < 8; j++) {
            int n = bN + tx * 8 + j;
            float v = acc[i][j] + bias[n];
            out[(size_t)(n >> 6) * SEQ * HD + (size_t)m * HD + (n & 63)] =
                __float2bfloat16(v);
        }
    }
}

// ---------------------------------------------------------------------------
// Causal attention with exact bf16-softmax emulation (XLA bf16 semantics):
//   s = bf16(q.k) * 0.5 (bf16), masked -inf
//   m = rowmax(s)                          [bf16 exact]
//   t = bf16(s - m); e = bf16(exp(t))
//   L = bf16(sum_f32(e))
//   p = bf16(e / L)
//   O = bf16(sum_f32 p*v)
// Phase 1: compute scores once -> g_S (bf16), row max.
// Phase 2: L from g_S.  Phase 3: probs + PV.
// One block per (q-tile of 64 rows, head). 256 threads, 4x4 micro-tiles.
// ---------------------------------------------------------------------------
__global__ __launch_bounds__(256) void attn_kernel()
{
    extern __shared__ float sm[];
    float* Qt   = sm;               // [64][72]  dim-major (transposed), padded
    float* Kt   = Qt + 64 * 72;     // [64][72]  dim-major (transposed), padded
    float* Vs   = Kt + 64 * 72;     // [64][64]  key-major
    float* Sb   = Vs + 64 * 64;     // [64][65]  scores/probs, padded
    float* mrow = Sb + 64 * 65;     // [64]
    float* lrow = mrow + 64;        // [64]
    float* psum = lrow + 64;        // [64][4]

    const int tid = threadIdx.x;
    const int tx = tid & 15, ty = tid >> 4;
    const int qt = blockIdx.x, h = blockIdx.y;
    const int r0 = ty * 4;          // local query rows
    const int c0 = tx * 4;          // local key cols (score phase)
    const int d0 = tx * 4;          // head dims (PV phase)
    const size_t qbase = ((size_t)h * SEQ + (size_t)qt * 64) * HD;
    const size_t srow0 = ((size_t)h * SEQ + (size_t)qt * 64) * SEQ; // g_S base
    const int len = (qt + 1) * 64;  // valid key length for this q-tile

    // Load Q tile (transposed to dim-major)
    for (int e = tid; e < 64 * HD; e += 256) {
        int r = e >> 6, d = e & 63;
        Qt[d * 72 + r] = __bfloat162float(g_Q[qbase + e]);
    }
    if (tid < 64) mrow[tid] = -INFINITY;
    __syncthreads();

    // ================= PHASE 1: scores -> g_S, row max =================
    for (int kt = 0; kt <= qt; kt++) {
        const size_t kbase = ((size_t)h * SEQ + (size_t)kt * 64) * HD;
        for (int e = tid; e < 64 * HD; e += 256) {
            int r = e >> 6, d = e & 63;
            Kt[d * 72 + r] = __bfloat162float(g_K[kbase + e]);
        }
        __syncthreads();

        float sacc[4][4] = {};
        #pragma unroll 16
        for (int kk = 0; kk < 64; kk++) {
            float4 qa = *(float4*)&Qt[kk * 72 + r0];
            float4 kb = *(float4*)&Kt[kk * 72 + c0];
            float qv[4] = {qa.x, qa.y, qa.z, qa.w};
            float kv[4] = {kb.x, kb.y, kb.z, kb.w};
            #pragma unroll
            for (int i = 0; i < 4; i++)
                #pragma unroll
                for (int j = 0; j < 4; j++)
                    sacc[i][j] = fmaf(qv[i], kv[j], sacc[i][j]);
        }
        const bool diag = (kt == qt);
        #pragma unroll
        for (int i = 0; i < 4; i++) {
            __nv_bfloat16 pk[4];
            #pragma unroll
            for (int j = 0; j < 4; j++) {
                // bf16 einsum output, then *0.5 (exact in bf16)
                float s = bf16r(sacc[i][j]) * 0.5f;
                if (diag && (c0 + j > r0 + i)) s = -INFINITY;
                pk[j] = __float2bfloat16(s);
                Sb[(r0 + i) * 65 + c0 + j] = s;
            }
            // packed 8B store of 4 bf16 scores
            *(uint2*)&g_S[srow0 + (size_t)(r0 + i) * SEQ + kt * 64 + c0] =
                *(uint2*)pk;
        }
        __syncthreads();

        if (tid < 64) {
            const int r = tid;
            float mx = mrow[r];
            for (int c = 0; c < 64; c++) mx = fmaxf(mx, Sb[r * 65 + c]);
            mrow[r] = mx;
        }
        __syncthreads();
    }

    // ================= PHASE 2: L = bf16(sum_f32 e) =================
    {
        const int r = tid >> 2, seg = tid & 3;
        const size_t rb = srow0 + (size_t)r * SEQ;
        const float m = mrow[r];
        float part = 0.f;
        for (int c = seg; c < len; c += 4) {
            float s = __bfloat162float(g_S[rb + c]);
            float t = bf16r(s - m);       // bf16 subtract
            part += bf16r(expf(t));       // bf16 exp, f32 accumulate
        }
        psum[r * 4 + seg] = part;
    }
    __syncthreads();
    if (tid < 64) {
        float L32 = ((psum[tid * 4 + 0] + psum[tid * 4 + 1]) +
                      psum[tid * 4 + 2]) + psum[tid * 4 + 3];
        lrow[tid] = bf16r(L32);           // bf16 reduce output
    }
    __syncthreads();

    // ================= PHASE 3: probs (bf16) and PV =================
    float acc[4][4] = {};
    float mfin[4], Lf[4];
    #pragma unroll
    for (int i = 0; i < 4; i++) {
        mfin[i] = mrow[r0 + i];
        Lf[i]   = lrow[r0 + i];
    }

    for (int kt = 0; kt <= qt; kt++) {
        const size_t kbase = ((size_t)h * SEQ + (size_t)kt * 64) * HD;
        for (int e = tid; e < 64 * HD; e += 256)
            Vs[e] = __bfloat162float(g_V[kbase + e]);

        // probs for this tile (read scores back from g_S)
        #pragma unroll
        for (int i = 0; i < 4; i++) {
            __nv_bfloat16 pk[4];
            *(uint2*)pk =
                *(uint2*)&g_S[srow0 + (size_t)(r0 + i) * SEQ + kt * 64 + c0];
            #pragma unroll
            for (int j = 0; j < 4; j++) {
                float s = __bfloat162float(pk[j]);
                float t = bf16r(s - mfin[i]);
                float e = bf16r(expf(t));
                Sb[(r0 + i) * 65 + c0 + j] = bf16r(e / Lf[i]);
            }
        }
        __syncthreads();

        #pragma unroll 8
        for (int k = 0; k < 64; k++) {
            float4 v4 = *(float4*)&Vs[k * 64 + d0];
            float vv[4] = {v4.x, v4.y, v4.z, v4.w};
            float pv[4];
            #pragma unroll
            for (int i = 0; i < 4; i++) pv[i] = Sb[(r0 + i) * 65 + k];
            #pragma unroll
            for (int i = 0; i < 4; i++)
                #pragma unroll
                for (int j = 0; j < 4; j++)
                    acc[i][j] = fmaf(pv[i], vv[j], acc[i][j]);
        }
        __syncthreads();
    }

    // Attention output materialized bf16 (like ref), then upcast to f32
    const int qg0 = qt * 64;
    #pragma unroll
    for (int i = 0; i < 4; i++)
        #pragma unroll
        for (int j = 0; j < 4; j++)
            g_attn[(size_t)(qg0 + r0 + i) * EMB + h * 64 + d0 + j] =
                bf16r(acc[i][j]);
}

// ---------------------------------------------------------------------------
// Output projection: out = g_attn @ Wo + bo (fp32)
// ---------------------------------------------------------------------------
__global__ __launch_bounds__(256) void out_proj_kernel(
    const float* __restrict__ Wo, const float* __restrict__ bo,
    float* __restrict__ outp)
{
    __shared__ float As[8][128];
    __shared__ float Bs[8][128];
    const int tid = threadIdx.x;
    const int tx = tid & 15, ty = tid >> 4;
    const int bM = blockIdx.y * 128, bN = blockIdx.x * 128;

    float acc[8][8] = {};

    for (int k0 = 0; k0 < EMB; k0 += 8) {
        {
            int ar = tid >> 1, ac = (tid & 1) * 4;
            float4 av = *(const float4*)(g_attn + (size_t)(bM + ar) * EMB + k0 + ac);
            As[ac + 0][ar] = av.x; As[ac + 1][ar] = av.y;
            As[ac + 2][ar] = av.z; As[ac + 3][ar] = av.w;
        }
        {
            int br = tid >> 5, bc = (tid & 31) * 4;
            *(float4*)&Bs[br][bc] =
                *(const float4*)(Wo + (size_t)(k0 + br) * EMB + bN + bc);
        }
        __syncthreads();
        #pragma unroll
        for (int kk = 0; kk < 8; kk++) {
            float a[8], b[8];
            *(float4*)&a[0] = *(float4*)&As[kk][ty * 8];
            *(float4*)&a[4] = *(float4*)&As[kk][ty * 8 + 4];
            *(float4*)&b[0] = *(float4*)&Bs[kk][tx * 8];
            *(float4*)&b[4] = *(float4*)&Bs[kk][tx * 8 + 4];
            #pragma unroll
            for (int i = 0; i < 8; i++)
                #pragma unroll
                for (int j = 0; j < 8; j++)
                    acc[i][j] = fmaf(a[i], b[j], acc[i][j]);
        }
        __syncthreads();
    }

    #pragma unroll
    for (int i = 0; i < 8; i++) {
        int m = bM + ty * 8 + i;
        #pragma unroll
        for (int j = 0; j < 8; j++) {
            int n = bN + tx * 8 + j;
            outp[(size_t)m * EMB + n] = acc[i][j] + bo[n];
        }
    }
}

// ---------------------------------------------------------------------------

extern "C" void kernel_launch(void* const* d_in, const int* in_sizes, int n_in,
                              void* d_out, int out_size)
{
    const float* x  = (const float*)d_in[0];
    const float* Wq = (const float*)d_in[1];
    const float* bq = (const float*)d_in[2];
    const float* Wk = (const float*)d_in[3];
    const float* bk = (const float*)d_in[4];
    const float* Wv = (const float*)d_in[5];
    const float* bv = (const float*)d_in[6];
    const float* Wo = (const float*)d_in[7];
    const float* bo = (const float*)d_in[8];
    float* out = (float*)d_out;

    const int attn_smem = (64 * 72 * 2 + 64 * 64 + 64 * 65 + 2 * 64 + 64 * 4) * 4;
    cudaFuncSetAttribute(attn_kernel,
                         cudaFuncAttributeMaxDynamicSharedMemorySize, attn_smem);

    dim3 blk(256);
    proj_qkv_kernel<<<dim3(EMB / 128, SEQ / 128, 3), blk>>>(x, Wq, bq, Wk, bk, Wv, bv);
    attn_kernel<<<dim3(SEQ / 64, NH), blk, attn_smem>>>();
    out_proj_kernel<<<dim3(EMB / 128, SEQ / 128), blk>>>(Wo, bo, out);
}

// round 4
// speedup vs baseline: 1.2605x; 1.2605x over previous
#include <cuda_runtime.h>
#include <cuda_bf16.h>
#include <math.h>
#include <stdint.h>

#define SEQ 2048
#define EMB 1024
#define NH  16
#define HD  64

// Scratch (device globals — no allocation allowed)
__device__ __nv_bfloat16 g_Q[NH * SEQ * HD];
__device__ __nv_bfloat16 g_K[NH * SEQ * HD];
__device__ __nv_bfloat16 g_V[NH * SEQ * HD];
__device__ __nv_bfloat16 g_S[(size_t)NH * SEQ * SEQ];   // masked bf16 scores
__device__ float g_attn[SEQ * EMB];

__device__ __forceinline__ float bf16r(float v) {
    return __bfloat162float(__float2bfloat16(v));
}

// ---------------- mma.sync helpers (bf16 -> f32) ----------------
__device__ __forceinline__ uint32_t smem_u32(const void* p) {
    return (uint32_t)__cvta_generic_to_shared(p);
}
__device__ __forceinline__ void ldsm_x4(uint32_t& a0, uint32_t& a1,
                                        uint32_t& a2, uint32_t& a3, uint32_t addr) {
    asm volatile("ldmatrix.sync.aligned.m8n8.x4.shared.b16 {%0,%1,%2,%3}, [%4];\n"
                 : "=r"(a0), "=r"(a1), "=r"(a2), "=r"(a3) : "r"(addr));
}
__device__ __forceinline__ void ldsm_x2(uint32_t& b0, uint32_t& b1, uint32_t addr) {
    asm volatile("ldmatrix.sync.aligned.m8n8.x2.shared.b16 {%0,%1}, [%2];\n"
                 : "=r"(b0), "=r"(b1) : "r"(addr));
}
__device__ __forceinline__ void ldsm_x2_t(uint32_t& b0, uint32_t& b1, uint32_t addr) {
    asm volatile("ldmatrix.sync.aligned.m8n8.x2.trans.shared.b16 {%0,%1}, [%2];\n"
                 : "=r"(b0), "=r"(b1) : "r"(addr));
}
__device__ __forceinline__ void mma16816(float& d0, float& d1, float& d2, float& d3,
                                         uint32_t a0, uint32_t a1, uint32_t a2, uint32_t a3,
                                         uint32_t b0, uint32_t b1) {
    asm volatile("mma.sync.aligned.m16n8k16.row.col.f32.bf16.bf16.f32 "
                 "{%0,%1,%2,%3},{%4,%5,%6,%7},{%8,%9},{%0,%1,%2,%3};\n"
                 : "+f"(d0), "+f"(d1), "+f"(d2), "+f"(d3)
                 : "r"(a0), "r"(a1), "r"(a2), "r"(a3), "r"(b0), "r"(b1));
}

// ---------------------------------------------------------------------------
// Fused QKV projection: P = x @ W + b, cast bf16, scatter into [H,S,D] layout.
// 128x128x8 register-blocked SGEMM, 256 threads, 8x8 micro-tile. (unchanged)
// ---------------------------------------------------------------------------
__global__ __launch_bounds__(256) void proj_qkv_kernel(
    const float* __restrict__ x,
    const float* __restrict__ Wq, const float* __restrict__ bq,
    const float* __restrict__ Wk, const float* __restrict__ bk,
    const float* __restrict__ Wv, const float* __restrict__ bv)
{
    const float* W; const float* bias; __nv_bfloat16* out;
    if (blockIdx.z == 0)      { W = Wq; bias = bq; out = g_Q; }
    else if (blockIdx.z == 1) { W = Wk; bias = bk; out = g_K; }
    else                      { W = Wv; bias = bv; out = g_V; }

    __shared__ float As[8][128];
    __shared__ float Bs[8][128];
    const int tid = threadIdx.x;
    const int tx = tid & 15, ty = tid >> 4;
    const int bM = blockIdx.y * 128, bN = blockIdx.x * 128;

    float acc[8][8] = {};

    for (int k0 = 0; k0 < EMB; k0 += 8) {
        {
            int ar = tid >> 1, ac = (tid & 1) * 4;
            float4 av = *(const float4*)(x + (size_t)(bM + ar) * EMB + k0 + ac);
            As[ac + 0][ar] = av.x; As[ac + 1][ar] = av.y;
            As[ac + 2][ar] = av.z; As[ac + 3][ar] = av.w;
        }
        {
            int br = tid >> 5, bc = (tid & 31) * 4;
            *(float4*)&Bs[br][bc] =
                *(const float4*)(W + (size_t)(k0 + br) * EMB + bN + bc);
        }
        __syncthreads();
        #pragma unroll
        for (int kk = 0; kk < 8; kk++) {
            float a[8], b[8];
            *(float4*)&a[0] = *(float4*)&As[kk][ty * 8];
            *(float4*)&a[4] = *(float4*)&As[kk][ty * 8 + 4];
            *(float4*)&b[0] = *(float4*)&Bs[kk][tx * 8];
            *(float4*)&b[4] = *(float4*)&Bs[kk][tx * 8 + 4];
            #pragma unroll
            for (int i = 0; i < 8; i++)
                #pragma unroll
                for (int j = 0; j < 8; j++)
                    acc[i][j] = fmaf(a[i], b[j], acc[i][j]);
        }
        __syncthreads();
    }

    #pragma unroll
    for (int i = 0; i < 8; i++) {
        int m = bM + ty * 8 + i;
        #pragma unroll
        for (int j = 0; j < 8; j++) {
            int n = bN + tx * 8 + j;
            float v = acc[i][j] + bias[n];
            out[(size_t)(n >> 6) * SEQ * HD + (size_t)m * HD + (n & 63)] =
                __float2bfloat16(v);
        }
    }
}

// ---------------------------------------------------------------------------
// Causal attention with exact bf16-softmax emulation, tensor-core matmuls.
//   Phase 1: S = bf16(QK^T)*0.5 via mma.sync -> g_S (bf16), row max in regs
//   Phase 2: L = bf16(sum_f32 bf16(exp(bf16(s-m))))  [identical to passing ker]
//   Phase 3: p = bf16(e/L) computed directly into MMA A-fragments; O = P@V mma
// Block: 128 threads = 4 warps; q-tile 64 rows (16 per warp), head = blockIdx.y
// ---------------------------------------------------------------------------
__global__ __launch_bounds__(128) void attn_kernel()
{
    __shared__ alignas(16) __nv_bfloat16 Qs[64 * 72];
    __shared__ alignas(16) __nv_bfloat16 KVs[64 * 72];   // K (ph1) then V (ph3)
    __shared__ float mrow[64];
    __shared__ float Lrow[64];
    __shared__ float psum[256];

    const int tid  = threadIdx.x;
    const int lane = tid & 31;
    const int warp = tid >> 5;
    const int r0   = warp * 16;                 // warp's local q-row base
    const int qt = blockIdx.x, h = blockIdx.y;
    const int len = (qt + 1) * 64;

    const size_t qbase = ((size_t)h * SEQ + (size_t)qt * 64) * HD;
    const size_t srow0 = ((size_t)h * SEQ + (size_t)qt * 64) * SEQ;

    // ---- load Q tile ----
    for (int idx = tid; idx < 64 * 8; idx += 128) {
        int r = idx >> 3, s = idx & 7;
        *(uint4*)&Qs[r * 72 + s * 8] = *(const uint4*)&g_Q[qbase + r * 64 + s * 8];
    }
    __syncthreads();

    // ---- A fragments for Q (constant across kt) ----
    uint32_t aq[4][4];
    {
        const uint32_t qb = smem_u32(Qs);
        #pragma unroll
        for (int ks = 0; ks < 4; ks++) {
            uint32_t addr = qb +
                (uint32_t)((r0 + (lane & 7) + ((lane >> 3) & 1) * 8) * 144 +
                           ((lane >> 4) * 16) + ks * 32);
            ldsm_x4(aq[ks][0], aq[ks][1], aq[ks][2], aq[ks][3], addr);
        }
    }

    // ================= PHASE 1: S -> g_S, running row max =================
    float rm0 = -INFINITY, rm1 = -INFINITY;
    const int rA = r0 + (lane >> 2);            // local row (and rA+8)
    const uint32_t kvb = smem_u32(KVs);

    for (int kt = 0; kt <= qt; kt++) {
        const size_t kbase = ((size_t)h * SEQ + (size_t)kt * 64) * HD;
        __syncthreads();
        for (int idx = tid; idx < 64 * 8; idx += 128) {
            int r = idx >> 3, s = idx & 7;
            *(uint4*)&KVs[r * 72 + s * 8] = *(const uint4*)&g_K[kbase + r * 64 + s * 8];
        }
        __syncthreads();

        const bool diag = (kt == qt);
        #pragma unroll
        for (int nt = 0; nt < 8; nt++) {
            float c0 = 0.f, c1 = 0.f, c2 = 0.f, c3 = 0.f;
            #pragma unroll
            for (int ks = 0; ks < 4; ks++) {
                int l2 = lane & 15;
                uint32_t addr = kvb +
                    (uint32_t)((nt * 8 + (l2 & 7)) * 144 + (l2 >> 3) * 16 + ks * 32);
                uint32_t b0, b1;
                ldsm_x2(b0, b1, addr);
                mma16816(c0, c1, c2, c3,
                         aq[ks][0], aq[ks][1], aq[ks][2], aq[ks][3], b0, b1);
            }
            // epilogue: bf16 round, *0.5, mask, pack, store; track max
            const int cc = nt * 8 + (lane & 3) * 2;     // local col (pair)
            float s00 = bf16r(c0) * 0.5f;
            float s01 = bf16r(c1) * 0.5f;
            float s10 = bf16r(c2) * 0.5f;
            float s11 = bf16r(c3) * 0.5f;
            if (diag) {
                if (cc     > rA)     s00 = -INFINITY;
                if (cc + 1 > rA)     s01 = -INFINITY;
                if (cc     > rA + 8) s10 = -INFINITY;
                if (cc + 1 > rA + 8) s11 = -INFINITY;
            }
            rm0 = fmaxf(rm0, fmaxf(s00, s01));
            rm1 = fmaxf(rm1, fmaxf(s10, s11));
            __nv_bfloat162 p0; p0.x = __float2bfloat16(s00); p0.y = __float2bfloat16(s01);
            __nv_bfloat162 p1; p1.x = __float2bfloat16(s10); p1.y = __float2bfloat16(s11);
            *(uint32_t*)&g_S[srow0 + (size_t)rA * SEQ + kt * 64 + cc]       = *(uint32_t*)&p0;
            *(uint32_t*)&g_S[srow0 + (size_t)(rA + 8) * SEQ + kt * 64 + cc] = *(uint32_t*)&p1;
        }
    }
    // quad-reduce row maxes (exact: fmaxf)
    rm0 = fmaxf(rm0, __shfl_xor_sync(0xFFFFFFFFu, rm0, 1));
    rm0 = fmaxf(rm0, __shfl_xor_sync(0xFFFFFFFFu, rm0, 2));
    rm1 = fmaxf(rm1, __shfl_xor_sync(0xFFFFFFFFu, rm1, 1));
    rm1 = fmaxf(rm1, __shfl_xor_sync(0xFFFFFFFFu, rm1, 2));
    if ((lane & 3) == 0) {
        mrow[rA]     = rm0;
        mrow[rA + 8] = rm1;
    }
    __syncthreads();

    // ================= PHASE 2: L = bf16(sum_f32 e)  (identical math) ======
    for (int rb = 0; rb < 64; rb += 32) {
        const int r = rb + (tid >> 2), seg = tid & 3;
        const size_t rbse = srow0 + (size_t)r * SEQ;
        const float m = mrow[r];
        float part = 0.f;
        for (int c = seg; c < len; c += 4) {
            float s = __bfloat162float(g_S[rbse + c]);
            float t = bf16r(s - m);
            part += bf16r(expf(t));
        }
        psum[r * 4 + seg] = part;
    }
    __syncthreads();
    if (tid < 64) {
        float L32 = ((psum[tid * 4 + 0] + psum[tid * 4 + 1]) +
                      psum[tid * 4 + 2]) + psum[tid * 4 + 3];
        Lrow[tid] = bf16r(L32);
    }
    __syncthreads();

    // ================= PHASE 3: probs -> A-frags, O = P @ V ================
    const float m0 = mrow[rA],     L0 = Lrow[rA];
    const float m1 = mrow[rA + 8], L1 = Lrow[rA + 8];
    const size_t srA = srow0 + (size_t)rA * SEQ;
    const size_t srB = srow0 + (size_t)(rA + 8) * SEQ;

    float o[8][4];
    #pragma unroll
    for (int nt = 0; nt < 8; nt++)
        #pragma unroll
        for (int i = 0; i < 4; i++) o[nt][i] = 0.f;

    for (int kt = 0; kt <= qt; kt++) {
        const size_t kbase = ((size_t)h * SEQ + (size_t)kt * 64) * HD;
        __syncthreads();
        for (int idx = tid; idx < 64 * 8; idx += 128) {
            int r = idx >> 3, s = idx & 7;
            *(uint4*)&KVs[r * 72 + s * 8] = *(const uint4*)&g_V[kbase + r * 64 + s * 8];
        }
        __syncthreads();

        // P fragments straight into A layout
        uint32_t pa[4][4];
        #pragma unroll
        for (int ks = 0; ks < 4; ks++) {
            const int col = kt * 64 + ks * 16 + (lane & 3) * 2;
            #pragma unroll
            for (int half = 0; half < 2; half++) {      // k, k+8
                uint32_t sA = *(const uint32_t*)&g_S[srA + col + half * 8];
                uint32_t sB = *(const uint32_t*)&g_S[srB + col + half * 8];
                __nv_bfloat162 svA = *(__nv_bfloat162*)&sA;
                __nv_bfloat162 svB = *(__nv_bfloat162*)&sB;
                float pA0 = bf16r(bf16r(expf(bf16r(__bfloat162float(svA.x) - m0))) / L0);
                float pA1 = bf16r(bf16r(expf(bf16r(__bfloat162float(svA.y) - m0))) / L0);
                float pB0 = bf16r(bf16r(expf(bf16r(__bfloat162float(svB.x) - m1))) / L1);
                float pB1 = bf16r(bf16r(expf(bf16r(__bfloat162float(svB.y) - m1))) / L1);
                __nv_bfloat162 fA; fA.x = __float2bfloat16(pA0); fA.y = __float2bfloat16(pA1);
                __nv_bfloat162 fB; fB.x = __float2bfloat16(pB0); fB.y = __float2bfloat16(pB1);
                pa[ks][half * 2 + 0] = *(uint32_t*)&fA;
                pa[ks][half * 2 + 1] = *(uint32_t*)&fB;
            }
        }

        #pragma unroll
        for (int nt = 0; nt < 8; nt++) {
            #pragma unroll
            for (int ks = 0; ks < 4; ks++) {
                int l2 = lane & 15;
                uint32_t addr = kvb + (uint32_t)((ks * 16 + l2) * 144 + nt * 16);
                uint32_t b0, b1;
                ldsm_x2_t(b0, b1, addr);
                mma16816(o[nt][0], o[nt][1], o[nt][2], o[nt][3],
                         pa[ks][0], pa[ks][1], pa[ks][2], pa[ks][3], b0, b1);
            }
        }
    }

    // write O (bf16-materialized like ref, upcast to f32)
    const int qg0 = qt * 64;
    #pragma unroll
    for (int nt = 0; nt < 8; nt++) {
        const int colb = h * 64 + nt * 8 + (lane & 3) * 2;
        float2 vA = make_float2(bf16r(o[nt][0]), bf16r(o[nt][1]));
        float2 vB = make_float2(bf16r(o[nt][2]), bf16r(o[nt][3]));
        *(float2*)&g_attn[(size_t)(qg0 + rA) * EMB + colb]     = vA;
        *(float2*)&g_attn[(size_t)(qg0 + rA + 8) * EMB + colb] = vB;
    }
}

// ---------------------------------------------------------------------------
// Output projection: out = g_attn @ Wo + bo (fp32)  (unchanged)
// ---------------------------------------------------------------------------
__global__ __launch_bounds__(256) void out_proj_kernel(
    const float* __restrict__ Wo, const float* __restrict__ bo,
    float* __restrict__ outp)
{
    __shared__ float As[8][128];
    __shared__ float Bs[8][128];
    const int tid = threadIdx.x;
    const int tx = tid & 15, ty = tid >> 4;
    const int bM = blockIdx.y * 128, bN = blockIdx.x * 128;

    float acc[8][8] = {};

    for (int k0 = 0; k0 < EMB; k0 += 8) {
        {
            int ar = tid >> 1, ac = (tid & 1) * 4;
            float4 av = *(const float4*)(g_attn + (size_t)(bM + ar) * EMB + k0 + ac);
            As[ac + 0][ar] = av.x; As[ac + 1][ar] = av.y;
            As[ac + 2][ar] = av.z; As[ac + 3][ar] = av.w;
        }
        {
            int br = tid >> 5, bc = (tid & 31) * 4;
            *(float4*)&Bs[br][bc] =
                *(const float4*)(Wo + (size_t)(k0 + br) * EMB + bN + bc);
        }
        __syncthreads();
        #pragma unroll
        for (int kk = 0; kk < 8; kk++) {
            float a[8], b[8];
            *(float4*)&a[0] = *(float4*)&As[kk][ty * 8];
            *(float4*)&a[4] = *(float4*)&As[kk][ty * 8 + 4];
            *(float4*)&b[0] = *(float4*)&Bs[kk][tx * 8];
            *(float4*)&b[4] = *(float4*)&Bs[kk][tx * 8 + 4];
            #pragma unroll
            for (int i = 0; i < 8; i++)
                #pragma unroll
                for (int j = 0; j < 8; j++)
                    acc[i][j] = fmaf(a[i], b[j], acc[i][j]);
        }
        __syncthreads();
    }

    #pragma unroll
    for (int i = 0; i < 8; i++) {
        int m = bM + ty * 8 + i;
        #pragma unroll
        for (int j = 0; j < 8; j++) {
            int n = bN + tx * 8 + j;
            outp[(size_t)m * EMB + n] = acc[i][j] + bo[n];
        }
    }
}

// ---------------------------------------------------------------------------

extern "C" void kernel_launch(void* const* d_in, const int* in_sizes, int n_in,
                              void* d_out, int out_size)
{
    const float* x  = (const float*)d_in[0];
    const float* Wq = (const float*)d_in[1];
    const float* bq = (const float*)d_in[2];
    const float* Wk = (const float*)d_in[3];
    const float* bk = (const float*)d_in[4];
    const float* Wv = (const float*)d_in[5];
    const float* bv = (const float*)d_in[6];
    const float* Wo = (const float*)d_in[7];
    const float* bo = (const float*)d_in[8];
    float* out = (float*)d_out;

    proj_qkv_kernel<<<dim3(EMB / 128, SEQ / 128, 3), 256>>>(x, Wq, bq, Wk, bk, Wv, bv);
    attn_kernel<<<dim3(SEQ / 64, NH), 128>>>();
    out_proj_kernel<<<dim3(EMB / 128, SEQ / 128), 256>>>(Wo, bo, out);
}

// round 7
// speedup vs baseline: 1.5207x; 1.2065x over previous
#include <cuda_runtime.h>
#include <cuda_bf16.h>
#include <math.h>
#include <stdint.h>

#define SEQ 2048
#define EMB 1024
#define NH  16
#define HD  64

// Scratch (device globals — no allocation allowed)
__device__ __nv_bfloat16 g_Q[NH * SEQ * HD];
__device__ __nv_bfloat16 g_K[NH * SEQ * HD];
__device__ __nv_bfloat16 g_V[NH * SEQ * HD];
__device__ __nv_bfloat16 g_S[(size_t)NH * SEQ * SEQ];   // masked bf16 scores
__device__ float g_attn[SEQ * EMB];

__device__ __forceinline__ float bf16r(float v) {
    return __bfloat162float(__float2bfloat16(v));
}
__device__ __forceinline__ uint32_t f2tf32(float x) {
    uint32_t r;
    asm("cvt.rna.tf32.f32 %0, %1;" : "=r"(r) : "f"(x));
    return r;
}

// ---------------- mma.sync helpers ----------------
__device__ __forceinline__ uint32_t smem_u32(const void* p) {
    return (uint32_t)__cvta_generic_to_shared(p);
}
__device__ __forceinline__ void ldsm_x4(uint32_t& a0, uint32_t& a1,
                                        uint32_t& a2, uint32_t& a3, uint32_t addr) {
    asm volatile("ldmatrix.sync.aligned.m8n8.x4.shared.b16 {%0,%1,%2,%3}, [%4];\n"
                 : "=r"(a0), "=r"(a1), "=r"(a2), "=r"(a3) : "r"(addr));
}
__device__ __forceinline__ void ldsm_x2(uint32_t& b0, uint32_t& b1, uint32_t addr) {
    asm volatile("ldmatrix.sync.aligned.m8n8.x2.shared.b16 {%0,%1}, [%2];\n"
                 : "=r"(b0), "=r"(b1) : "r"(addr));
}
__device__ __forceinline__ void ldsm_x2_t(uint32_t& b0, uint32_t& b1, uint32_t addr) {
    asm volatile("ldmatrix.sync.aligned.m8n8.x2.trans.shared.b16 {%0,%1}, [%2];\n"
                 : "=r"(b0), "=r"(b1) : "r"(addr));
}
__device__ __forceinline__ void mma16816(float& d0, float& d1, float& d2, float& d3,
                                         uint32_t a0, uint32_t a1, uint32_t a2, uint32_t a3,
                                         uint32_t b0, uint32_t b1) {
    asm volatile("mma.sync.aligned.m16n8k16.row.col.f32.bf16.bf16.f32 "
                 "{%0,%1,%2,%3},{%4,%5,%6,%7},{%8,%9},{%0,%1,%2,%3};\n"
                 : "+f"(d0), "+f"(d1), "+f"(d2), "+f"(d3)
                 : "r"(a0), "r"(a1), "r"(a2), "r"(a3), "r"(b0), "r"(b1));
}
__device__ __forceinline__ void mma_tf32(float* d, const uint32_t* a,
                                         const uint32_t* b) {
    asm volatile("mma.sync.aligned.m16n8k8.row.col.f32.tf32.tf32.f32 "
                 "{%0,%1,%2,%3},{%4,%5,%6,%7},{%8,%9},{%0,%1,%2,%3};\n"
                 : "+f"(d[0]), "+f"(d[1]), "+f"(d[2]), "+f"(d[3])
                 : "r"(a[0]), "r"(a[1]), "r"(a[2]), "r"(a[3]), "r"(b[0]), "r"(b[1]));
}

// ---------------------------------------------------------------------------
// Fused QKV projection (ROUND-4 NUMERICS, bitwise identical accumulation):
// 128x128x8 register-blocked fp32 SGEMM + register prefetch of the next
// k-tile (pure latency hiding; FFMA sequence per accumulator unchanged).
// ---------------------------------------------------------------------------
__global__ __launch_bounds__(256) void proj_qkv_kernel(
    const float* __restrict__ x,
    const float* __restrict__ Wq, const float* __restrict__ bq,
    const float* __restrict__ Wk, const float* __restrict__ bk,
    const float* __restrict__ Wv, const float* __restrict__ bv)
{
    const float* W; const float* bias; __nv_bfloat16* out;
    if (blockIdx.z == 0)      { W = Wq; bias = bq; out = g_Q; }
    else if (blockIdx.z == 1) { W = Wk; bias = bk; out = g_K; }
    else                      { W = Wv; bias = bv; out = g_V; }

    __shared__ float As[8][128];
    __shared__ float Bs[8][128];
    const int tid = threadIdx.x;
    const int tx = tid & 15, ty = tid >> 4;
    const int bM = blockIdx.y * 128, bN = blockIdx.x * 128;

    const int ar = tid >> 1, ac = (tid & 1) * 4;      // A staging coords
    const int br = tid >> 5, bc = (tid & 31) * 4;     // B staging coords

    float acc[8][8] = {};

    // prologue: stage k0 = 0
    float4 pa = *(const float4*)(x + (size_t)(bM + ar) * EMB + ac);
    float4 pb = *(const float4*)(W + (size_t)br * EMB + bN + bc);

    for (int k0 = 0; k0 < EMB; k0 += 8) {
        As[ac + 0][ar] = pa.x; As[ac + 1][ar] = pa.y;
        As[ac + 2][ar] = pa.z; As[ac + 3][ar] = pa.w;
        *(float4*)&Bs[br][bc] = pb;
        __syncthreads();

        if (k0 + 8 < EMB) {   // prefetch next tile while computing this one
            pa = *(const float4*)(x + (size_t)(bM + ar) * EMB + k0 + 8 + ac);
            pb = *(const float4*)(W + (size_t)(k0 + 8 + br) * EMB + bN + bc);
        }

        #pragma unroll
        for (int kk = 0; kk < 8; kk++) {
            float a[8], b[8];
            *(float4*)&a[0] = *(float4*)&As[kk][ty * 8];
            *(float4*)&a[4] = *(float4*)&As[kk][ty * 8 + 4];
            *(float4*)&b[0] = *(float4*)&Bs[kk][tx * 8];
            *(float4*)&b[4] = *(float4*)&Bs[kk][tx * 8 + 4];
            #pragma unroll
            for (int i = 0; i < 8; i++)
                #pragma unroll
                for (int j = 0; j < 8; j++)
                    acc[i][j] = fmaf(a[i], b[j], acc[i][j]);
        }
        __syncthreads();
    }

    #pragma unroll
    for (int i = 0; i < 8; i++) {
        int m = bM + ty * 8 + i;
        #pragma unroll
        for (int j = 0; j < 8; j++) {
            int n = bN + tx * 8 + j;
            float v = acc[i][j] + bias[n];
            out[(size_t)(n >> 6) * SEQ * HD + (size_t)m * HD + (n & 63)] =
                __float2bfloat16(v);
        }
    }
}

// ---------------------------------------------------------------------------
// Causal attention — BYTE-FOR-BYTE the round-4 passing version.
// Phase 1: S = bf16(QK^T)*0.5 -> g_S, row max. Phase 2: L = bf16(sum_f32 e).
// Phase 3: p = bf16(bf16(exp(bf16(s-m)))/L) recomputed, O = P@V.
// One block per (q-tile of 64 rows, head). 128 threads = 4 warps.
// ---------------------------------------------------------------------------
__global__ __launch_bounds__(128) void attn_kernel()
{
    __shared__ alignas(16) __nv_bfloat16 Qs[64 * 72];
    __shared__ alignas(16) __nv_bfloat16 KVs[64 * 72];
    __shared__ float mrow[64];
    __shared__ float Lrow[64];
    __shared__ float psum[256];

    const int tid  = threadIdx.x;
    const int lane = tid & 31;
    const int warp = tid >> 5;
    const int r0   = warp * 16;
    const int qt = blockIdx.x, h = blockIdx.y;
    const int len = (qt + 1) * 64;

    const size_t qbase = ((size_t)h * SEQ + (size_t)qt * 64) * HD;
    const size_t srow0 = ((size_t)h * SEQ + (size_t)qt * 64) * SEQ;

    for (int idx = tid; idx < 64 * 8; idx += 128) {
        int r = idx >> 3, s = idx & 7;
        *(uint4*)&Qs[r * 72 + s * 8] = *(const uint4*)&g_Q[qbase + r * 64 + s * 8];
    }
    __syncthreads();

    uint32_t aq[4][4];
    {
        const uint32_t qb = smem_u32(Qs);
        #pragma unroll
        for (int ks = 0; ks < 4; ks++) {
            uint32_t addr = qb +
                (uint32_t)((r0 + (lane & 7) + ((lane >> 3) & 1) * 8) * 144 +
                           ((lane >> 4) * 16) + ks * 32);
            ldsm_x4(aq[ks][0], aq[ks][1], aq[ks][2], aq[ks][3], addr);
        }
    }

    // ================= PHASE 1: S -> g_S, running row max =================
    float rm0 = -INFINITY, rm1 = -INFINITY;
    const int rA = r0 + (lane >> 2);
    const uint32_t kvb = smem_u32(KVs);

    for (int kt = 0; kt <= qt; kt++) {
        const size_t kbase = ((size_t)h * SEQ + (size_t)kt * 64) * HD;
        __syncthreads();
        for (int idx = tid; idx < 64 * 8; idx += 128) {
            int r = idx >> 3, s = idx & 7;
            *(uint4*)&KVs[r * 72 + s * 8] = *(const uint4*)&g_K[kbase + r * 64 + s * 8];
        }
        __syncthreads();

        const bool diag = (kt == qt);
        #pragma unroll
        for (int nt = 0; nt < 8; nt++) {
            float c0 = 0.f, c1 = 0.f, c2 = 0.f, c3 = 0.f;
            #pragma unroll
            for (int ks = 0; ks < 4; ks++) {
                int l2 = lane & 15;
                uint32_t addr = kvb +
                    (uint32_t)((nt * 8 + (l2 & 7)) * 144 + (l2 >> 3) * 16 + ks * 32);
                uint32_t b0, b1;
                ldsm_x2(b0, b1, addr);
                mma16816(c0, c1, c2, c3,
                         aq[ks][0], aq[ks][1], aq[ks][2], aq[ks][3], b0, b1);
            }
            const int cc = nt * 8 + (lane & 3) * 2;
            float s00 = bf16r(c0) * 0.5f;
            float s01 = bf16r(c1) * 0.5f;
            float s10 = bf16r(c2) * 0.5f;
            float s11 = bf16r(c3) * 0.5f;
            if (diag) {
                if (cc     > rA)     s00 = -INFINITY;
                if (cc + 1 > rA)     s01 = -INFINITY;
                if (cc     > rA + 8) s10 = -INFINITY;
                if (cc + 1 > rA + 8) s11 = -INFINITY;
            }
            rm0 = fmaxf(rm0, fmaxf(s00, s01));
            rm1 = fmaxf(rm1, fmaxf(s10, s11));
            __nv_bfloat162 p0; p0.x = __float2bfloat16(s00); p0.y = __float2bfloat16(s01);
            __nv_bfloat162 p1; p1.x = __float2bfloat16(s10); p1.y = __float2bfloat16(s11);
            *(uint32_t*)&g_S[srow0 + (size_t)rA * SEQ + kt * 64 + cc]       = *(uint32_t*)&p0;
            *(uint32_t*)&g_S[srow0 + (size_t)(rA + 8) * SEQ + kt * 64 + cc] = *(uint32_t*)&p1;
        }
    }
    rm0 = fmaxf(rm0, __shfl_xor_sync(0xFFFFFFFFu, rm0, 1));
    rm0 = fmaxf(rm0, __shfl_xor_sync(0xFFFFFFFFu, rm0, 2));
    rm1 = fmaxf(rm1, __shfl_xor_sync(0xFFFFFFFFu, rm1, 1));
    rm1 = fmaxf(rm1, __shfl_xor_sync(0xFFFFFFFFu, rm1, 2));
    if ((lane & 3) == 0) {
        mrow[rA]     = rm0;
        mrow[rA + 8] = rm1;
    }
    __syncthreads();

    // ================= PHASE 2: L = bf16(sum_f32 e) =================
    for (int rb = 0; rb < 64; rb += 32) {
        const int r = rb + (tid >> 2), seg = tid & 3;
        const size_t rbse = srow0 + (size_t)r * SEQ;
        const float m = mrow[r];
        float part = 0.f;
        for (int c = seg; c < len; c += 4) {
            float s = __bfloat162float(g_S[rbse + c]);
            float t = bf16r(s - m);
            part += bf16r(expf(t));
        }
        psum[r * 4 + seg] = part;
    }
    __syncthreads();
    if (tid < 64) {
        float L32 = ((psum[tid * 4 + 0] + psum[tid * 4 + 1]) +
                      psum[tid * 4 + 2]) + psum[tid * 4 + 3];
        Lrow[tid] = bf16r(L32);
    }
    __syncthreads();

    // ================= PHASE 3: probs -> A-frags, O = P @ V ================
    const float m0 = mrow[rA],     L0 = Lrow[rA];
    const float m1 = mrow[rA + 8], L1 = Lrow[rA + 8];
    const size_t srA = srow0 + (size_t)rA * SEQ;
    const size_t srB = srow0 + (size_t)(rA + 8) * SEQ;

    float o[8][4];
    #pragma unroll
    for (int nt = 0; nt < 8; nt++)
        #pragma unroll
        for (int i = 0; i < 4; i++) o[nt][i] = 0.f;

    for (int kt = 0; kt <= qt; kt++) {
        const size_t kbase = ((size_t)h * SEQ + (size_t)kt * 64) * HD;
        __syncthreads();
        for (int idx = tid; idx < 64 * 8; idx += 128) {
            int r = idx >> 3, s = idx & 7;
            *(uint4*)&KVs[r * 72 + s * 8] = *(const uint4*)&g_V[kbase + r * 64 + s * 8];
        }
        __syncthreads();

        uint32_t pa[4][4];
        #pragma unroll
        for (int ks = 0; ks < 4; ks++) {
            const int col = kt * 64 + ks * 16 + (lane & 3) * 2;
            #pragma unroll
            for (int half = 0; half < 2; half++) {
                uint32_t sA = *(const uint32_t*)&g_S[srA + col + half * 8];
                uint32_t sB = *(const uint32_t*)&g_S[srB + col + half * 8];
                __nv_bfloat162 svA = *(__nv_bfloat162*)&sA;
                __nv_bfloat162 svB = *(__nv_bfloat162*)&sB;
                float pA0 = bf16r(bf16r(expf(bf16r(__bfloat162float(svA.x) - m0))) / L0);
                float pA1 = bf16r(bf16r(expf(bf16r(__bfloat162float(svA.y) - m0))) / L0);
                float pB0 = bf16r(bf16r(expf(bf16r(__bfloat162float(svB.x) - m1))) / L1);
                float pB1 = bf16r(bf16r(expf(bf16r(__bfloat162float(svB.y) - m1))) / L1);
                __nv_bfloat162 fA; fA.x = __float2bfloat16(pA0); fA.y = __float2bfloat16(pA1);
                __nv_bfloat162 fB; fB.x = __float2bfloat16(pB0); fB.y = __float2bfloat16(pB1);
                pa[ks][half * 2 + 0] = *(uint32_t*)&fA;
                pa[ks][half * 2 + 1] = *(uint32_t*)&fB;
            }
        }

        #pragma unroll
        for (int nt = 0; nt < 8; nt++) {
            #pragma unroll
            for (int ks = 0; ks < 4; ks++) {
                int l2 = lane & 15;
                uint32_t addr = kvb + (uint32_t)((ks * 16 + l2) * 144 + nt * 16);
                uint32_t b0, b1;
                ldsm_x2_t(b0, b1, addr);
                mma16816(o[nt][0], o[nt][1], o[nt][2], o[nt][3],
                         pa[ks][0], pa[ks][1], pa[ks][2], pa[ks][3], b0, b1);
            }
        }
    }

    const int qg0 = qt * 64;
    #pragma unroll
    for (int nt = 0; nt < 8; nt++) {
        const int colb = h * 64 + nt * 8 + (lane & 3) * 2;
        float2 vA = make_float2(bf16r(o[nt][0]), bf16r(o[nt][1]));
        float2 vB = make_float2(bf16r(o[nt][2]), bf16r(o[nt][3]));
        *(float2*)&g_attn[(size_t)(qg0 + rA) * EMB + colb]     = vA;
        *(float2*)&g_attn[(size_t)(qg0 + rA + 8) * EMB + colb] = vB;
    }
}

// ---------------------------------------------------------------------------
// Output projection, 2xTF32 (THE single numerics change this round):
// A = g_attn values are exactly bf16 -> tf32 conversion exact; Wo split h/l.
// ---------------------------------------------------------------------------
#define ASTR 36
#define BSTR 136

__global__ __launch_bounds__(256) void out_proj_tf32(
    const float* __restrict__ Wo, const float* __restrict__ bo,
    float* __restrict__ outp)
{
    extern __shared__ uint32_t dsm[];
    uint32_t* Ah = dsm;                    // [128][ASTR]
    uint32_t* Bh = Ah + 128 * ASTR;        // [32][BSTR]
    uint32_t* Bl = Bh + 32 * BSTR;

    const int tid = threadIdx.x, lane = tid & 31, warp = tid >> 5;
    const int wm = warp >> 2, wn = warp & 3;
    const int g = lane >> 2, t = lane & 3;
    const int bM = blockIdx.y * 128, bN = blockIdx.x * 128;

    float acc[4][4][4] = {};

    for (int k0 = 0; k0 < EMB; k0 += 32) {
        #pragma unroll
        for (int u = 0; u < 4; u++) {
            int idx = tid + u * 256;
            int row = idx >> 3, c4 = (idx & 7) * 4;
            float4 v = *(const float4*)(g_attn + (size_t)(bM + row) * EMB + k0 + c4);
            uint4 h;
            h.x = f2tf32(v.x); h.y = f2tf32(v.y);
            h.z = f2tf32(v.z); h.w = f2tf32(v.w);
            *(uint4*)&Ah[row * ASTR + c4] = h;
        }
        #pragma unroll
        for (int u = 0; u < 4; u++) {
            int idx = tid + u * 256;
            int kr = idx >> 5, c4 = (idx & 31) * 4;
            float4 v = *(const float4*)(Wo + (size_t)(k0 + kr) * EMB + bN + c4);
            uint4 h, l;
            h.x = f2tf32(v.x); l.x = f2tf32(v.x - __uint_as_float(h.x));
            h.y = f2tf32(v.y); l.y = f2tf32(v.y - __uint_as_float(h.y));
            h.z = f2tf32(v.z); l.z = f2tf32(v.z - __uint_as_float(h.z));
            h.w = f2tf32(v.w); l.w = f2tf32(v.w - __uint_as_float(h.w));
            *(uint4*)&Bh[kr * BSTR + c4] = h;
            *(uint4*)&Bl[kr * BSTR + c4] = l;
        }
        __syncthreads();

        #pragma unroll
        for (int ks = 0; ks < 4; ks++) {
            uint32_t ah[4][4], bh[4][2], bl[4][2];
            #pragma unroll
            for (int mi = 0; mi < 4; mi++) {
                int base = (wm * 64 + mi * 16 + g) * ASTR + ks * 8 + t;
                ah[mi][0] = Ah[base];
                ah[mi][1] = Ah[base + 8 * ASTR];
                ah[mi][2] = Ah[base + 4];
                ah[mi][3] = Ah[base + 8 * ASTR + 4];
            }
            #pragma unroll
            for (int nj = 0; nj < 4; nj++) {
                int base = (ks * 8 + t) * BSTR + wn * 32 + nj * 8 + g;
                bh[nj][0] = Bh[base];
                bh[nj][1] = Bh[base + 4 * BSTR];
                bl[nj][0] = Bl[base];
                bl[nj][1] = Bl[base + 4 * BSTR];
            }
            #pragma unroll
            for (int mi = 0; mi < 4; mi++)
                #pragma unroll
                for (int nj = 0; nj < 4; nj++) {
                    mma_tf32(acc[mi][nj], ah[mi], bh[nj]);
                    mma_tf32(acc[mi][nj], ah[mi], bl[nj]);
                }
        }
        __syncthreads();
    }

    #pragma unroll
    for (int mi = 0; mi < 4; mi++) {
        #pragma unroll
        for (int nj = 0; nj < 4; nj++) {
            int m0r = bM + wm * 64 + mi * 16 + g;
            int n   = bN + wn * 32 + nj * 8 + t * 2;
            float b0 = bo[n], b1 = bo[n + 1];
            float2 v0 = make_float2(acc[mi][nj][0] + b0, acc[mi][nj][1] + b1);
            float2 v1 = make_float2(acc[mi][nj][2] + b0, acc[mi][nj][3] + b1);
            *(float2*)&outp[(size_t)m0r * EMB + n]       = v0;
            *(float2*)&outp[(size_t)(m0r + 8) * EMB + n] = v1;
        }
    }
}

// ---------------------------------------------------------------------------

extern "C" void kernel_launch(void* const* d_in, const int* in_sizes, int n_in,
                              void* d_out, int out_size)
{
    const float* x  = (const float*)d_in[0];
    const float* Wq = (const float*)d_in[1];
    const float* bq = (const float*)d_in[2];
    const float* Wk = (const float*)d_in[3];
    const float* bk = (const float*)d_in[4];
    const float* Wv = (const float*)d_in[5];
    const float* bv = (const float*)d_in[6];
    const float* Wo = (const float*)d_in[7];
    const float* bo = (const float*)d_in[8];
    float* out = (float*)d_out;

    const int outp_smem = (128 * ASTR + 32 * BSTR * 2) * 4;       // 53248 B
    cudaFuncSetAttribute(out_proj_tf32,
                         cudaFuncAttributeMaxDynamicSharedMemorySize, outp_smem);

    proj_qkv_kernel<<<dim3(EMB / 128, SEQ / 128, 3), 256>>>(x, Wq, bq, Wk, bk, Wv, bv);
    attn_kernel<<<dim3(SEQ / 64, NH), 128>>>();
    out_proj_tf32<<<dim3(EMB / 128, SEQ / 128), 256, outp_smem>>>(Wo, bo, out);
}

// round 9
// speedup vs baseline: 1.6269x; 1.0698x over previous
#include <cuda_runtime.h>
#include <cuda_bf16.h>
#include <math.h>
#include <stdint.h>

#define SEQ 2048
#define EMB 1024
#define NH  16
#define HD  64

// Scratch (device globals — no allocation allowed)
__device__ __nv_bfloat16 g_Q[NH * SEQ * HD];
__device__ __nv_bfloat16 g_K[NH * SEQ * HD];
__device__ __nv_bfloat16 g_V[NH * SEQ * HD];
__device__ __nv_bfloat16 g_S[(size_t)NH * SEQ * SEQ];   // scores, then exp values
__device__ float g_attn[SEQ * EMB];

__device__ __forceinline__ float bf16r(float v) {
    return __bfloat162float(__float2bfloat16(v));
}
__device__ __forceinline__ uint32_t f2tf32(float x) {
    uint32_t r;
    asm("cvt.rna.tf32.f32 %0, %1;" : "=r"(r) : "f"(x));
    return r;
}

// ---------------- mma.sync helpers ----------------
__device__ __forceinline__ uint32_t smem_u32(const void* p) {
    return (uint32_t)__cvta_generic_to_shared(p);
}
__device__ __forceinline__ void ldsm_x4(uint32_t& a0, uint32_t& a1,
                                        uint32_t& a2, uint32_t& a3, uint32_t addr) {
    asm volatile("ldmatrix.sync.aligned.m8n8.x4.shared.b16 {%0,%1,%2,%3}, [%4];\n"
                 : "=r"(a0), "=r"(a1), "=r"(a2), "=r"(a3) : "r"(addr));
}
__device__ __forceinline__ void ldsm_x2(uint32_t& b0, uint32_t& b1, uint32_t addr) {
    asm volatile("ldmatrix.sync.aligned.m8n8.x2.shared.b16 {%0,%1}, [%2];\n"
                 : "=r"(b0), "=r"(b1) : "r"(addr));
}
__device__ __forceinline__ void ldsm_x2_t(uint32_t& b0, uint32_t& b1, uint32_t addr) {
    asm volatile("ldmatrix.sync.aligned.m8n8.x2.trans.shared.b16 {%0,%1}, [%2];\n"
                 : "=r"(b0), "=r"(b1) : "r"(addr));
}
__device__ __forceinline__ void mma16816(float& d0, float& d1, float& d2, float& d3,
                                         uint32_t a0, uint32_t a1, uint32_t a2, uint32_t a3,
                                         uint32_t b0, uint32_t b1) {
    asm volatile("mma.sync.aligned.m16n8k16.row.col.f32.bf16.bf16.f32 "
                 "{%0,%1,%2,%3},{%4,%5,%6,%7},{%8,%9},{%0,%1,%2,%3};\n"
                 : "+f"(d0), "+f"(d1), "+f"(d2), "+f"(d3)
                 : "r"(a0), "r"(a1), "r"(a2), "r"(a3), "r"(b0), "r"(b1));
}
__device__ __forceinline__ void mma_tf32(float* d, const uint32_t* a,
                                         const uint32_t* b) {
    asm volatile("mma.sync.aligned.m16n8k8.row.col.f32.tf32.tf32.f32 "
                 "{%0,%1,%2,%3},{%4,%5,%6,%7},{%8,%9},{%0,%1,%2,%3};\n"
                 : "+f"(d[0]), "+f"(d[1]), "+f"(d[2]), "+f"(d[3])
                 : "r"(a[0]), "r"(a[1]), "r"(a[2]), "r"(a[3]), "r"(b[0]), "r"(b[1]));
}

// ---------------- cp.async helpers ----------------
__device__ __forceinline__ void cp_async16(uint32_t smem_addr, const void* gptr) {
    asm volatile("cp.async.cg.shared.global [%0], [%1], 16;\n"
                 :: "r"(smem_addr), "l"(gptr));
}
__device__ __forceinline__ void cp_commit() {
    asm volatile("cp.async.commit_group;\n" ::: "memory");
}
__device__ __forceinline__ void cp_wait0() {
    asm volatile("cp.async.wait_group 0;\n" ::: "memory");
}

// ---------------------------------------------------------------------------
// Fused QKV projection — EXACT round-7 version (FFMA, at fma-pipe roofline).
// ---------------------------------------------------------------------------
__global__ __launch_bounds__(256) void proj_qkv_kernel(
    const float* __restrict__ x,
    const float* __restrict__ Wq, const float* __restrict__ bq,
    const float* __restrict__ Wk, const float* __restrict__ bk,
    const float* __restrict__ Wv, const float* __restrict__ bv)
{
    const float* W; const float* bias; __nv_bfloat16* out;
    if (blockIdx.z == 0)      { W = Wq; bias = bq; out = g_Q; }
    else if (blockIdx.z == 1) { W = Wk; bias = bk; out = g_K; }
    else                      { W = Wv; bias = bv; out = g_V; }

    __shared__ float As[8][128];
    __shared__ float Bs[8][128];
    const int tid = threadIdx.x;
    const int tx = tid & 15, ty = tid >> 4;
    const int bM = blockIdx.y * 128, bN = blockIdx.x * 128;

    const int ar = tid >> 1, ac = (tid & 1) * 4;
    const int br = tid >> 5, bc = (tid & 31) * 4;

    float acc[8][8] = {};

    float4 pa = *(const float4*)(x + (size_t)(bM + ar) * EMB + ac);
    float4 pb = *(const float4*)(W + (size_t)br * EMB + bN + bc);

    for (int k0 = 0; k0 < EMB; k0 += 8) {
        As[ac + 0][ar] = pa.x; As[ac + 1][ar] = pa.y;
        As[ac + 2][ar] = pa.z; As[ac + 3][ar] = pa.w;
        *(float4*)&Bs[br][bc] = pb;
        __syncthreads();

        if (k0 + 8 < EMB) {
            pa = *(const float4*)(x + (size_t)(bM + ar) * EMB + k0 + 8 + ac);
            pb = *(const float4*)(W + (size_t)(k0 + 8 + br) * EMB + bN + bc);
        }

        #pragma unroll
        for (int kk = 0; kk < 8; kk++) {
            float a[8], b[8];
            *(float4*)&a[0] = *(float4*)&As[kk][ty * 8];
            *(float4*)&a[4] = *(float4*)&As[kk][ty * 8 + 4];
            *(float4*)&b[0] = *(float4*)&Bs[kk][tx * 8];
            *(float4*)&b[4] = *(float4*)&Bs[kk][tx * 8 + 4];
            #pragma unroll
            for (int i = 0; i < 8; i++)
                #pragma unroll
                for (int j = 0; j < 8; j++)
                    acc[i][j] = fmaf(a[i], b[j], acc[i][j]);
        }
        __syncthreads();
    }

    #pragma unroll
    for (int i = 0; i < 8; i++) {
        int m = bM + ty * 8 + i;
        #pragma unroll
        for (int j = 0; j < 8; j++) {
            int n = bN + tx * 8 + j;
            float v = acc[i][j] + bias[n];
            out[(size_t)(n >> 6) * SEQ * HD + (size_t)m * HD + (n & 63)] =
                __float2bfloat16(v);
        }
    }
}

// ---------------------------------------------------------------------------
// Causal attention, bf16-softmax-exact. Numerics proven bit-identical to the
// round-4/7 pass (pairing + e-store validated by rounds 6==8). cp.async
// double-buffered K/V tile loads added (non-numeric).
// ---------------------------------------------------------------------------
__device__ __forceinline__ void stage_tile(uint32_t dst, const __nv_bfloat16* src) {
    const int tid = threadIdx.x;
    #pragma unroll
    for (int u = 0; u < 4; u++) {
        int idx = tid + u * 128;
        int r = idx >> 3, s = idx & 7;
        cp_async16(dst + (uint32_t)((r * 72 + s * 8) * 2), src + r * 64 + s * 8);
    }
}

__device__ __forceinline__ void attn_qtile(
    int qt, int h, __nv_bfloat16* Qs, __nv_bfloat16 (*KV2)[64 * 72],
    float* mrow, float* Lrow, float* psum)
{
    const int tid  = threadIdx.x;
    const int lane = tid & 31;
    const int warp = tid >> 5;
    const int r0   = warp * 16;
    const int len  = (qt + 1) * 64;

    const size_t qbase = ((size_t)h * SEQ + (size_t)qt * 64) * HD;
    const size_t srow0 = ((size_t)h * SEQ + (size_t)qt * 64) * SEQ;
    const __nv_bfloat16* Kh = g_K + (size_t)h * SEQ * HD;
    const __nv_bfloat16* Vh = g_V + (size_t)h * SEQ * HD;

    const uint32_t kvb0 = smem_u32(&KV2[0][0]);
    const uint32_t kvb1 = smem_u32(&KV2[1][0]);

    // ---- load Q tile ----
    for (int idx = tid; idx < 64 * 8; idx += 128) {
        int r = idx >> 3, s = idx & 7;
        *(uint4*)&Qs[r * 72 + s * 8] = *(const uint4*)&g_Q[qbase + r * 64 + s * 8];
    }
    __syncthreads();

    uint32_t aq[4][4];
    {
        const uint32_t qb = smem_u32(Qs);
        #pragma unroll
        for (int ks = 0; ks < 4; ks++) {
            uint32_t addr = qb +
                (uint32_t)((r0 + (lane & 7) + ((lane >> 3) & 1) * 8) * 144 +
                           ((lane >> 4) * 16) + ks * 32);
            ldsm_x4(aq[ks][0], aq[ks][1], aq[ks][2], aq[ks][3], addr);
        }
    }

    // ================= PHASE 1: S -> g_S, running row max =================
    float rm0 = -INFINITY, rm1 = -INFINITY;
    const int rA = r0 + (lane >> 2);

    stage_tile(kvb0, Kh);                   // prefetch kt = 0
    cp_commit();

    for (int kt = 0; kt <= qt; kt++) {
        cp_wait0();
        __syncthreads();
        const uint32_t kvb = (kt & 1) ? kvb1 : kvb0;
        if (kt < qt) {
            stage_tile((kt & 1) ? kvb0 : kvb1, Kh + (size_t)(kt + 1) * 64 * HD);
            cp_commit();
        }

        const bool diag = (kt == qt);
        #pragma unroll
        for (int nt = 0; nt < 8; nt++) {
            float c0 = 0.f, c1 = 0.f, c2 = 0.f, c3 = 0.f;
            #pragma unroll
            for (int ks = 0; ks < 4; ks++) {
                int l2 = lane & 15;
                uint32_t addr = kvb +
                    (uint32_t)((nt * 8 + (l2 & 7)) * 144 + (l2 >> 3) * 16 + ks * 32);
                uint32_t b0, b1;
                ldsm_x2(b0, b1, addr);
                mma16816(c0, c1, c2, c3,
                         aq[ks][0], aq[ks][1], aq[ks][2], aq[ks][3], b0, b1);
            }
            const int cc = nt * 8 + (lane & 3) * 2;
            float s00 = bf16r(c0) * 0.5f;
            float s01 = bf16r(c1) * 0.5f;
            float s10 = bf16r(c2) * 0.5f;
            float s11 = bf16r(c3) * 0.5f;
            if (diag) {
                if (cc     > rA)     s00 = -INFINITY;
                if (cc + 1 > rA)     s01 = -INFINITY;
                if (cc     > rA + 8) s10 = -INFINITY;
                if (cc + 1 > rA + 8) s11 = -INFINITY;
            }
            rm0 = fmaxf(rm0, fmaxf(s00, s01));
            rm1 = fmaxf(rm1, fmaxf(s10, s11));
            __nv_bfloat162 p0; p0.x = __float2bfloat16(s00); p0.y = __float2bfloat16(s01);
            __nv_bfloat162 p1; p1.x = __float2bfloat16(s10); p1.y = __float2bfloat16(s11);
            *(uint32_t*)&g_S[srow0 + (size_t)rA * SEQ + kt * 64 + cc]       = *(uint32_t*)&p0;
            *(uint32_t*)&g_S[srow0 + (size_t)(rA + 8) * SEQ + kt * 64 + cc] = *(uint32_t*)&p1;
        }
    }
    rm0 = fmaxf(rm0, __shfl_xor_sync(0xFFFFFFFFu, rm0, 1));
    rm0 = fmaxf(rm0, __shfl_xor_sync(0xFFFFFFFFu, rm0, 2));
    rm1 = fmaxf(rm1, __shfl_xor_sync(0xFFFFFFFFu, rm1, 1));
    rm1 = fmaxf(rm1, __shfl_xor_sync(0xFFFFFFFFu, rm1, 2));
    if ((lane & 3) == 0) {
        mrow[rA]     = rm0;
        mrow[rA + 8] = rm1;
    }
    __syncthreads();

    // ====== PHASE 2: e stored to g_S; L = bf16(sum_f32 e) (same order) =====
    for (int rb = 0; rb < 64; rb += 32) {
        const int r = rb + (tid >> 2), seg = tid & 3;
        const size_t rbse = srow0 + (size_t)r * SEQ;
        const float m = mrow[r];
        float part = 0.f;
        for (int c = seg; c < len; c += 4) {
            float s = __bfloat162float(g_S[rbse + c]);
            float t = bf16r(s - m);
            float e = bf16r(expf(t));
            part += e;
            g_S[rbse + c] = __float2bfloat16(e);
        }
        psum[r * 4 + seg] = part;
    }
    __syncthreads();
    if (tid < 64) {
        float L32 = ((psum[tid * 4 + 0] + psum[tid * 4 + 1]) +
                      psum[tid * 4 + 2]) + psum[tid * 4 + 3];
        Lrow[tid] = bf16r(L32);
    }
    __syncthreads();

    // ================= PHASE 3: p = bf16(e/L) -> A-frags, O = P @ V ========
    const float L0 = Lrow[rA];
    const float L1 = Lrow[rA + 8];
    const size_t srA = srow0 + (size_t)rA * SEQ;
    const size_t srB = srow0 + (size_t)(rA + 8) * SEQ;

    float o[8][4];
    #pragma unroll
    for (int nt = 0; nt < 8; nt++)
        #pragma unroll
        for (int i = 0; i < 4; i++) o[nt][i] = 0.f;

    stage_tile(kvb0, Vh);                   // prefetch kt = 0
    cp_commit();

    for (int kt = 0; kt <= qt; kt++) {
        cp_wait0();
        __syncthreads();
        const uint32_t kvb = (kt & 1) ? kvb1 : kvb0;
        if (kt < qt) {
            stage_tile((kt & 1) ? kvb0 : kvb1, Vh + (size_t)(kt + 1) * 64 * HD);
            cp_commit();
        }

        uint32_t pa[4][4];
        #pragma unroll
        for (int ks = 0; ks < 4; ks++) {
            const int col = kt * 64 + ks * 16 + (lane & 3) * 2;
            #pragma unroll
            for (int half = 0; half < 2; half++) {
                uint32_t sA = *(const uint32_t*)&g_S[srA + col + half * 8];
                uint32_t sB = *(const uint32_t*)&g_S[srB + col + half * 8];
                __nv_bfloat162 eA = *(__nv_bfloat162*)&sA;
                __nv_bfloat162 eB = *(__nv_bfloat162*)&sB;
                __nv_bfloat162 fA, fB;
                fA.x = __float2bfloat16(__bfloat162float(eA.x) / L0);
                fA.y = __float2bfloat16(__bfloat162float(eA.y) / L0);
                fB.x = __float2bfloat16(__bfloat162float(eB.x) / L1);
                fB.y = __float2bfloat16(__bfloat162float(eB.y) / L1);
                pa[ks][half * 2 + 0] = *(uint32_t*)&fA;
                pa[ks][half * 2 + 1] = *(uint32_t*)&fB;
            }
        }

        #pragma unroll
        for (int nt = 0; nt < 8; nt++) {
            #pragma unroll
            for (int ks = 0; ks < 4; ks++) {
                int l2 = lane & 15;
                uint32_t addr = kvb + (uint32_t)((ks * 16 + l2) * 144 + nt * 16);
                uint32_t b0, b1;
                ldsm_x2_t(b0, b1, addr);
                mma16816(o[nt][0], o[nt][1], o[nt][2], o[nt][3],
                         pa[ks][0], pa[ks][1], pa[ks][2], pa[ks][3], b0, b1);
            }
        }
    }

    const int qg0 = qt * 64;
    #pragma unroll
    for (int nt = 0; nt < 8; nt++) {
        const int colb = h * 64 + nt * 8 + (lane & 3) * 2;
        float2 vA = make_float2(bf16r(o[nt][0]), bf16r(o[nt][1]));
        float2 vB = make_float2(bf16r(o[nt][2]), bf16r(o[nt][3]));
        *(float2*)&g_attn[(size_t)(qg0 + rA) * EMB + colb]     = vA;
        *(float2*)&g_attn[(size_t)(qg0 + rA + 8) * EMB + colb] = vB;
    }
}

__global__ __launch_bounds__(128) void attn_kernel()
{
    __shared__ alignas(16) __nv_bfloat16 Qs[64 * 72];
    __shared__ alignas(16) __nv_bfloat16 KV2[2][64 * 72];
    __shared__ float mrow[64];
    __shared__ float Lrow[64];
    __shared__ float psum[256];

    const int h = blockIdx.y;
    attn_qtile((int)blockIdx.x, h, Qs, KV2, mrow, Lrow, psum);
    __syncthreads();
    attn_qtile(31 - (int)blockIdx.x, h, Qs, KV2, mrow, Lrow, psum);
}

// ---------------------------------------------------------------------------
// Output projection, 2xTF32 — EXACT round-7 version (validated).
// ---------------------------------------------------------------------------
#define ASTR 36
#define BSTR 136

__global__ __launch_bounds__(256) void out_proj_tf32(
    const float* __restrict__ Wo, const float* __restrict__ bo,
    float* __restrict__ outp)
{
    extern __shared__ uint32_t dsm[];
    uint32_t* Ah = dsm;                    // [128][ASTR]
    uint32_t* Bh = Ah + 128 * ASTR;        // [32][BSTR]
    uint32_t* Bl = Bh + 32 * BSTR;

    const int tid = threadIdx.x, lane = tid & 31, warp = tid >> 5;
    const int wm = warp >> 2, wn = warp & 3;
    const int g = lane >> 2, t = lane & 3;
    const int bM = blockIdx.y * 128, bN = blockIdx.x * 128;

    float acc[4][4][4] = {};

    for (int k0 = 0; k0 < EMB; k0 += 32) {
        #pragma unroll
        for (int u = 0; u < 4; u++) {
            int idx = tid + u * 256;
            int row = idx >> 3, c4 = (idx & 7) * 4;
            float4 v = *(const float4*)(g_attn + (size_t)(bM + row) * EMB + k0 + c4);
            uint4 h;
            h.x = f2tf32(v.x); h.y = f2tf32(v.y);
            h.z = f2tf32(v.z); h.w = f2tf32(v.w);
            *(uint4*)&Ah[row * ASTR + c4] = h;
        }
        #pragma unroll
        for (int u = 0; u < 4; u++) {
            int idx = tid + u * 256;
            int kr = idx >> 5, c4 = (idx & 31) * 4;
            float4 v = *(const float4*)(Wo + (size_t)(k0 + kr) * EMB + bN + c4);
            uint4 h, l;
            h.x = f2tf32(v.x); l.x = f2tf32(v.x - __uint_as_float(h.x));
            h.y = f2tf32(v.y); l.y = f2tf32(v.y - __uint_as_float(h.y));
            h.z = f2tf32(v.z); l.z = f2tf32(v.z - __uint_as_float(h.z));
            h.w = f2tf32(v.w); l.w = f2tf32(v.w - __uint_as_float(h.w));
            *(uint4*)&Bh[kr * BSTR + c4] = h;
            *(uint4*)&Bl[kr * BSTR + c4] = l;
        }
        __syncthreads();

        #pragma unroll
        for (int ks = 0; ks < 4; ks++) {
            uint32_t ah[4][4], bh[4][2], bl[4][2];
            #pragma unroll
            for (int mi = 0; mi < 4; mi++) {
                int base = (wm * 64 + mi * 16 + g) * ASTR + ks * 8 + t;
                ah[mi][0] = Ah[base];
                ah[mi][1] = Ah[base + 8 * ASTR];
                ah[mi][2] = Ah[base + 4];
                ah[mi][3] = Ah[base + 8 * ASTR + 4];
            }
            #pragma unroll
            for (int nj = 0; nj < 4; nj++) {
                int base = (ks * 8 + t) * BSTR + wn * 32 + nj * 8 + g;
                bh[nj][0] = Bh[base];
                bh[nj][1] = Bh[base + 4 * BSTR];
                bl[nj][0] = Bl[base];
                bl[nj][1] = Bl[base + 4 * BSTR];
            }
            #pragma unroll
            for (int mi = 0; mi < 4; mi++)
                #pragma unroll
                for (int nj = 0; nj < 4; nj++) {
                    mma_tf32(acc[mi][nj], ah[mi], bh[nj]);
                    mma_tf32(acc[mi][nj], ah[mi], bl[nj]);
                }
        }
        __syncthreads();
    }

    #pragma unroll
    for (int mi = 0; mi < 4; mi++) {
        #pragma unroll
        for (int nj = 0; nj < 4; nj++) {
            int m0r = bM + wm * 64 + mi * 16 + g;
            int n   = bN + wn * 32 + nj * 8 + t * 2;
            float b0 = bo[n], b1 = bo[n + 1];
            float2 v0 = make_float2(acc[mi][nj][0] + b0, acc[mi][nj][1] + b1);
            float2 v1 = make_float2(acc[mi][nj][2] + b0, acc[mi][nj][3] + b1);
            *(float2*)&outp[(size_t)m0r * EMB + n]       = v0;
            *(float2*)&outp[(size_t)(m0r + 8) * EMB + n] = v1;
        }
    }
}

// ---------------------------------------------------------------------------

extern "C" void kernel_launch(void* const* d_in, const int* in_sizes, int n_in,
                              void* d_out, int out_size)
{
    const float* x  = (const float*)d_in[0];
    const float* Wq = (const float*)d_in[1];
    const float* bq = (const float*)d_in[2];
    const float* Wk = (const float*)d_in[3];
    const float* bk = (const float*)d_in[4];
    const float* Wv = (const float*)d_in[5];
    const float* bv = (const float*)d_in[6];
    const float* Wo = (const float*)d_in[7];
    const float* bo = (const float*)d_in[8];
    float* out = (float*)d_out;

    const int outp_smem = (128 * ASTR + 32 * BSTR * 2) * 4;       // 53248 B
    cudaFuncSetAttribute(out_proj_tf32,
                         cudaFuncAttributeMaxDynamicSharedMemorySize, outp_smem);

    proj_qkv_kernel<<<dim3(EMB / 128, SEQ / 128, 3), 256>>>(x, Wq, bq, Wk, bk, Wv, bv);
    attn_kernel<<<dim3(16, NH), 128>>>();
    out_proj_tf32<<<dim3(EMB / 128, SEQ / 128), 256, outp_smem>>>(Wo, bo, out);
}

// round 11
// speedup vs baseline: 1.6495x; 1.0139x over previous
#include <cuda_runtime.h>
#include <cuda_bf16.h>
#include <math.h>
#include <stdint.h>

#define SEQ 2048
#define EMB 1024
#define NH  16
#define HD  64

// Scratch (device globals — no allocation allowed)
__device__ __nv_bfloat16 g_Q[NH * SEQ * HD];
__device__ __nv_bfloat16 g_K[NH * SEQ * HD];
__device__ __nv_bfloat16 g_V[NH * SEQ * HD];
__device__ __nv_bfloat16 g_S[(size_t)NH * SEQ * SEQ];   // scores, then exp values
__device__ float g_attn[SEQ * EMB];

__device__ __forceinline__ float bf16r(float v) {
    return __bfloat162float(__float2bfloat16(v));
}
__device__ __forceinline__ uint32_t f2tf32(float x) {
    uint32_t r;
    asm("cvt.rna.tf32.f32 %0, %1;" : "=r"(r) : "f"(x));
    return r;
}

// ---------------- mma.sync helpers ----------------
__device__ __forceinline__ uint32_t smem_u32(const void* p) {
    return (uint32_t)__cvta_generic_to_shared(p);
}
__device__ __forceinline__ void ldsm_x4(uint32_t& a0, uint32_t& a1,
                                        uint32_t& a2, uint32_t& a3, uint32_t addr) {
    asm volatile("ldmatrix.sync.aligned.m8n8.x4.shared.b16 {%0,%1,%2,%3}, [%4];\n"
                 : "=r"(a0), "=r"(a1), "=r"(a2), "=r"(a3) : "r"(addr));
}
__device__ __forceinline__ void ldsm_x2(uint32_t& b0, uint32_t& b1, uint32_t addr) {
    asm volatile("ldmatrix.sync.aligned.m8n8.x2.shared.b16 {%0,%1}, [%2];\n"
                 : "=r"(b0), "=r"(b1) : "r"(addr));
}
__device__ __forceinline__ void ldsm_x2_t(uint32_t& b0, uint32_t& b1, uint32_t addr) {
    asm volatile("ldmatrix.sync.aligned.m8n8.x2.trans.shared.b16 {%0,%1}, [%2];\n"
                 : "=r"(b0), "=r"(b1) : "r"(addr));
}
__device__ __forceinline__ void mma16816(float& d0, float& d1, float& d2, float& d3,
                                         uint32_t a0, uint32_t a1, uint32_t a2, uint32_t a3,
                                         uint32_t b0, uint32_t b1) {
    asm volatile("mma.sync.aligned.m16n8k16.row.col.f32.bf16.bf16.f32 "
                 "{%0,%1,%2,%3},{%4,%5,%6,%7},{%8,%9},{%0,%1,%2,%3};\n"
                 : "+f"(d0), "+f"(d1), "+f"(d2), "+f"(d3)
                 : "r"(a0), "r"(a1), "r"(a2), "r"(a3), "r"(b0), "r"(b1));
}
__device__ __forceinline__ void mma_tf32(float* d, const uint32_t* a,
                                         const uint32_t* b) {
    asm volatile("mma.sync.aligned.m16n8k8.row.col.f32.tf32.tf32.f32 "
                 "{%0,%1,%2,%3},{%4,%5,%6,%7},{%8,%9},{%0,%1,%2,%3};\n"
                 : "+f"(d[0]), "+f"(d[1]), "+f"(d[2]), "+f"(d[3])
                 : "r"(a[0]), "r"(a[1]), "r"(a[2]), "r"(a[3]), "r"(b[0]), "r"(b[1]));
}

// ---------------- cp.async helpers ----------------
__device__ __forceinline__ void cp_async16(uint32_t smem_addr, const void* gptr) {
    asm volatile("cp.async.cg.shared.global [%0], [%1], 16;\n"
                 :: "r"(smem_addr), "l"(gptr));
}
__device__ __forceinline__ void cp_commit() {
    asm volatile("cp.async.commit_group;\n" ::: "memory");
}
__device__ __forceinline__ void cp_wait0() {
    asm volatile("cp.async.wait_group 0;\n" ::: "memory");
}
__device__ __forceinline__ void bar_sync(int id) {
    asm volatile("bar.sync %0, 128;\n" :: "r"(id) : "memory");
}

// ---------------------------------------------------------------------------
// Fused QKV projection — round-7 FFMA numerics (sequential-K, bit-exact vs
// reference), now with single-sync double-buffered smem tiles.
// ---------------------------------------------------------------------------
__global__ __launch_bounds__(256) void proj_qkv_kernel(
    const float* __restrict__ x,
    const float* __restrict__ Wq, const float* __restrict__ bq,
    const float* __restrict__ Wk, const float* __restrict__ bk,
    const float* __restrict__ Wv, const float* __restrict__ bv)
{
    const float* W; const float* bias; __nv_bfloat16* out;
    if (blockIdx.z == 0)      { W = Wq; bias = bq; out = g_Q; }
    else if (blockIdx.z == 1) { W = Wk; bias = bk; out = g_K; }
    else                      { W = Wv; bias = bv; out = g_V; }

    __shared__ float As[2][8][128];
    __shared__ float Bs[2][8][128];
    const int tid = threadIdx.x;
    const int tx = tid & 15, ty = tid >> 4;
    const int bM = blockIdx.y * 128, bN = blockIdx.x * 128;

    const int ar = tid >> 1, ac = (tid & 1) * 4;
    const int br = tid >> 5, bc = (tid & 31) * 4;

    float acc[8][8] = {};

    float4 pa = *(const float4*)(x + (size_t)(bM + ar) * EMB + ac);
    float4 pb = *(const float4*)(W + (size_t)br * EMB + bN + bc);

    for (int k0 = 0; k0 < EMB; k0 += 8) {
        const int b = (k0 >> 3) & 1;
        As[b][ac + 0][ar] = pa.x; As[b][ac + 1][ar] = pa.y;
        As[b][ac + 2][ar] = pa.z; As[b][ac + 3][ar] = pa.w;
        *(float4*)&Bs[b][br][bc] = pb;
        __syncthreads();

        if (k0 + 8 < EMB) {
            pa = *(const float4*)(x + (size_t)(bM + ar) * EMB + k0 + 8 + ac);
            pb = *(const float4*)(W + (size_t)(k0 + 8 + br) * EMB + bN + bc);
        }

        #pragma unroll
        for (int kk = 0; kk < 8; kk++) {
            float a[8], bb[8];
            *(float4*)&a[0]  = *(float4*)&As[b][kk][ty * 8];
            *(float4*)&a[4]  = *(float4*)&As[b][kk][ty * 8 + 4];
            *(float4*)&bb[0] = *(float4*)&Bs[b][kk][tx * 8];
            *(float4*)&bb[4] = *(float4*)&Bs[b][kk][tx * 8 + 4];
            #pragma unroll
            for (int i = 0; i < 8; i++)
                #pragma unroll
                for (int j = 0; j < 8; j++)
                    acc[i][j] = fmaf(a[i], bb[j], acc[i][j]);
        }
        // no trailing sync: next iteration writes the other buffer; its
        // leading sync orders buffer reuse two iterations apart.
    }

    #pragma unroll
    for (int i = 0; i < 8; i++) {
        int m = bM + ty * 8 + i;
        #pragma unroll
        for (int j = 0; j < 8; j++) {
            int n = bN + tx * 8 + j;
            float v = acc[i][j] + bias[n];
            out[(size_t)(n >> 6) * SEQ * HD + (size_t)m * HD + (n & 63)] =
                __float2bfloat16(v);
        }
    }
}

// ---------------------------------------------------------------------------
// Causal attention — per-q-tile code is byte-identical math to round 9
// (proven bit-safe). Now TWO warpgroups per block: WG0 does q-tile b, WG1
// does 31-b, on disjoint smem with per-WG named barriers. cp.async K/V
// double buffering as in round 9.
// ---------------------------------------------------------------------------
__device__ __forceinline__ void stage_tile(uint32_t dst, const __nv_bfloat16* src,
                                           int wtid) {
    #pragma unroll
    for (int u = 0; u < 4; u++) {
        int idx = wtid + u * 128;
        int r = idx >> 3, s = idx & 7;
        cp_async16(dst + (uint32_t)((r * 72 + s * 8) * 2), src + r * 64 + s * 8);
    }
}

__device__ void attn_qtile(
    int qt, int h, __nv_bfloat16* Qs, __nv_bfloat16* KV2,
    float* mrow, float* Lrow, float* psum, int wtid, int barid)
{
    const int lane = wtid & 31;
    const int warp = wtid >> 5;
    const int r0   = warp * 16;
    const int len  = (qt + 1) * 64;

    const size_t qbase = ((size_t)h * SEQ + (size_t)qt * 64) * HD;
    const size_t srow0 = ((size_t)h * SEQ + (size_t)qt * 64) * SEQ;
    const __nv_bfloat16* Kh = g_K + (size_t)h * SEQ * HD;
    const __nv_bfloat16* Vh = g_V + (size_t)h * SEQ * HD;

    const uint32_t kvb0 = smem_u32(KV2);
    const uint32_t kvb1 = kvb0 + 64 * 72 * 2;

    for (int idx = wtid; idx < 64 * 8; idx += 128) {
        int r = idx >> 3, s = idx & 7;
        *(uint4*)&Qs[r * 72 + s * 8] = *(const uint4*)&g_Q[qbase + r * 64 + s * 8];
    }
    bar_sync(barid);

    uint32_t aq[4][4];
    {
        const uint32_t qb = smem_u32(Qs);
        #pragma unroll
        for (int ks = 0; ks < 4; ks++) {
            uint32_t addr = qb +
                (uint32_t)((r0 + (lane & 7) + ((lane >> 3) & 1) * 8) * 144 +
                           ((lane >> 4) * 16) + ks * 32);
            ldsm_x4(aq[ks][0], aq[ks][1], aq[ks][2], aq[ks][3], addr);
        }
    }

    // ================= PHASE 1: S -> g_S, running row max =================
    float rm0 = -INFINITY, rm1 = -INFINITY;
    const int rA = r0 + (lane >> 2);

    stage_tile(kvb0, Kh, wtid);
    cp_commit();

    for (int kt = 0; kt <= qt; kt++) {
        cp_wait0();
        bar_sync(barid);
        const uint32_t kvb = (kt & 1) ? kvb1 : kvb0;
        if (kt < qt) {
            stage_tile((kt & 1) ? kvb0 : kvb1, Kh + (size_t)(kt + 1) * 64 * HD, wtid);
            cp_commit();
        }

        const bool diag = (kt == qt);
        #pragma unroll
        for (int nt = 0; nt < 8; nt++) {
            float c0 = 0.f, c1 = 0.f, c2 = 0.f, c3 = 0.f;
            #pragma unroll
            for (int ks = 0; ks < 4; ks++) {
                int l2 = lane & 15;
                uint32_t addr = kvb +
                    (uint32_t)((nt * 8 + (l2 & 7)) * 144 + (l2 >> 3) * 16 + ks * 32);
                uint32_t b0, b1;
                ldsm_x2(b0, b1, addr);
                mma16816(c0, c1, c2, c3,
                         aq[ks][0], aq[ks][1], aq[ks][2], aq[ks][3], b0, b1);
            }
            const int cc = nt * 8 + (lane & 3) * 2;
            float s00 = bf16r(c0) * 0.5f;
            float s01 = bf16r(c1) * 0.5f;
            float s10 = bf16r(c2) * 0.5f;
            float s11 = bf16r(c3) * 0.5f;
            if (diag) {
                if (cc     > rA)     s00 = -INFINITY;
                if (cc + 1 > rA)     s01 = -INFINITY;
                if (cc     > rA + 8) s10 = -INFINITY;
                if (cc + 1 > rA + 8) s11 = -INFINITY;
            }
            rm0 = fmaxf(rm0, fmaxf(s00, s01));
            rm1 = fmaxf(rm1, fmaxf(s10, s11));
            __nv_bfloat162 p0; p0.x = __float2bfloat16(s00); p0.y = __float2bfloat16(s01);
            __nv_bfloat162 p1; p1.x = __float2bfloat16(s10); p1.y = __float2bfloat16(s11);
            *(uint32_t*)&g_S[srow0 + (size_t)rA * SEQ + kt * 64 + cc]       = *(uint32_t*)&p0;
            *(uint32_t*)&g_S[srow0 + (size_t)(rA + 8) * SEQ + kt * 64 + cc] = *(uint32_t*)&p1;
        }
    }
    rm0 = fmaxf(rm0, __shfl_xor_sync(0xFFFFFFFFu, rm0, 1));
    rm0 = fmaxf(rm0, __shfl_xor_sync(0xFFFFFFFFu, rm0, 2));
    rm1 = fmaxf(rm1, __shfl_xor_sync(0xFFFFFFFFu, rm1, 1));
    rm1 = fmaxf(rm1, __shfl_xor_sync(0xFFFFFFFFu, rm1, 2));
    if ((lane & 3) == 0) {
        mrow[rA]     = rm0;
        mrow[rA + 8] = rm1;
    }
    bar_sync(barid);

    // ====== PHASE 2: e stored to g_S; L = bf16(sum_f32 e) (same order) =====
    for (int rb = 0; rb < 64; rb += 32) {
        const int r = rb + (wtid >> 2), seg = wtid & 3;
        const size_t rbse = srow0 + (size_t)r * SEQ;
        const float m = mrow[r];
        float part = 0.f;
        for (int c = seg; c < len; c += 4) {
            float s = __bfloat162float(g_S[rbse + c]);
            float t = bf16r(s - m);
            float e = bf16r(expf(t));
            part += e;
            g_S[rbse + c] = __float2bfloat16(e);
        }
        psum[r * 4 + seg] = part;
    }
    bar_sync(barid);
    if (wtid < 64) {
        float L32 = ((psum[wtid * 4 + 0] + psum[wtid * 4 + 1]) +
                      psum[wtid * 4 + 2]) + psum[wtid * 4 + 3];
        Lrow[wtid] = bf16r(L32);
    }
    bar_sync(barid);

    // ================= PHASE 3: p = bf16(e/L) -> A-frags, O = P @ V ========
    const float L0 = Lrow[rA];
    const float L1 = Lrow[rA + 8];
    const size_t srA = srow0 + (size_t)rA * SEQ;
    const size_t srB = srow0 + (size_t)(rA + 8) * SEQ;

    float o[8][4];
    #pragma unroll
    for (int nt = 0; nt < 8; nt++)
        #pragma unroll
        for (int i = 0; i < 4; i++) o[nt][i] = 0.f;

    stage_tile(kvb0, Vh, wtid);
    cp_commit();

    for (int kt = 0; kt <= qt; kt++) {
        cp_wait0();
        bar_sync(barid);
        const uint32_t kvb = (kt & 1) ? kvb1 : kvb0;
        if (kt < qt) {
            stage_tile((kt & 1) ? kvb0 : kvb1, Vh + (size_t)(kt + 1) * 64 * HD, wtid);
            cp_commit();
        }

        uint32_t pa[4][4];
        #pragma unroll
        for (int ks = 0; ks < 4; ks++) {
            const int col = kt * 64 + ks * 16 + (lane & 3) * 2;
            #pragma unroll
            for (int half = 0; half < 2; half++) {
                uint32_t sA = *(const uint32_t*)&g_S[srA + col + half * 8];
                uint32_t sB = *(const uint32_t*)&g_S[srB + col + half * 8];
                __nv_bfloat162 eA = *(__nv_bfloat162*)&sA;
                __nv_bfloat162 eB = *(__nv_bfloat162*)&sB;
                __nv_bfloat162 fA, fB;
                fA.x = __float2bfloat16(__bfloat162float(eA.x) / L0);
                fA.y = __float2bfloat16(__bfloat162float(eA.y) / L0);
                fB.x = __float2bfloat16(__bfloat162float(eB.x) / L1);
                fB.y = __float2bfloat16(__bfloat162float(eB.y) / L1);
                pa[ks][half * 2 + 0] = *(uint32_t*)&fA;
                pa[ks][half * 2 + 1] = *(uint32_t*)&fB;
            }
        }

        #pragma unroll
        for (int nt = 0; nt < 8; nt++) {
            #pragma unroll
            for (int ks = 0; ks < 4; ks++) {
                int l2 = lane & 15;
                uint32_t addr = kvb + (uint32_t)((ks * 16 + l2) * 144 + nt * 16);
                uint32_t b0, b1;
                ldsm_x2_t(b0, b1, addr);
                mma16816(o[nt][0], o[nt][1], o[nt][2], o[nt][3],
                         pa[ks][0], pa[ks][1], pa[ks][2], pa[ks][3], b0, b1);
            }
        }
    }

    const int qg0 = qt * 64;
    #pragma unroll
    for (int nt = 0; nt < 8; nt++) {
        const int colb = h * 64 + nt * 8 + (lane & 3) * 2;
        float2 vA = make_float2(bf16r(o[nt][0]), bf16r(o[nt][1]));
        float2 vB = make_float2(bf16r(o[nt][2]), bf16r(o[nt][3]));
        *(float2*)&g_attn[(size_t)(qg0 + rA) * EMB + colb]     = vA;
        *(float2*)&g_attn[(size_t)(qg0 + rA + 8) * EMB + colb] = vB;
    }
}

// per-WG smem partition: Qs 9216 B, KV2 18432 B, mrow 256, Lrow 256, psum 1024
#define WG_SMEM (9216 + 18432 + 256 + 256 + 1024)   // 29184 B

__global__ __launch_bounds__(256) void attn_kernel()
{
    extern __shared__ char asm_smem[];
    const int wg   = threadIdx.x >> 7;     // 0 or 1
    const int wtid = threadIdx.x & 127;

    char* base = asm_smem + wg * WG_SMEM;
    __nv_bfloat16* Qs  = (__nv_bfloat16*)base;
    __nv_bfloat16* KV2 = (__nv_bfloat16*)(base + 9216);
    float* mrow = (float*)(base + 9216 + 18432);
    float* Lrow = mrow + 64;
    float* psum = Lrow + 64;

    const int h  = blockIdx.y;
    const int qt = wg ? (31 - (int)blockIdx.x) : (int)blockIdx.x;
    attn_qtile(qt, h, Qs, KV2, mrow, Lrow, psum, wtid, wg + 1);
}

// ---------------------------------------------------------------------------
// Output projection, 2xTF32 — EXACT round-7/9 version (validated).
// ---------------------------------------------------------------------------
#define ASTR 36
#define BSTR 136

__global__ __launch_bounds__(256) void out_proj_tf32(
    const float* __restrict__ Wo, const float* __restrict__ bo,
    float* __restrict__ outp)
{
    extern __shared__ uint32_t dsm[];
    uint32_t* Ah = dsm;                    // [128][ASTR]
    uint32_t* Bh = Ah + 128 * ASTR;        // [32][BSTR]
    uint32_t* Bl = Bh + 32 * BSTR;

    const int tid = threadIdx.x, lane = tid & 31, warp = tid >> 5;
    const int wm = warp >> 2, wn = warp & 3;
    const int g = lane >> 2, t = lane & 3;
    const int bM = blockIdx.y * 128, bN = blockIdx.x * 128;

    float acc[4][4][4] = {};

    for (int k0 = 0; k0 < EMB; k0 += 32) {
        #pragma unroll
        for (int u = 0; u < 4; u++) {
            int idx = tid + u * 256;
            int row = idx >> 3, c4 = (idx & 7) * 4;
            float4 v = *(const float4*)(g_attn + (size_t)(bM + row) * EMB + k0 + c4);
            uint4 h;
            h.x = f2tf32(v.x); h.y = f2tf32(v.y);
            h.z = f2tf32(v.z); h.w = f2tf32(v.w);
            *(uint4*)&Ah[row * ASTR + c4] = h;
        }
        #pragma unroll
        for (int u = 0; u < 4; u++) {
            int idx = tid + u * 256;
            int kr = idx >> 5, c4 = (idx & 31) * 4;
            float4 v = *(const float4*)(Wo + (size_t)(k0 + kr) * EMB + bN + c4);
            uint4 h, l;
            h.x = f2tf32(v.x); l.x = f2tf32(v.x - __uint_as_float(h.x));
            h.y = f2tf32(v.y); l.y = f2tf32(v.y - __uint_as_float(h.y));
            h.z = f2tf32(v.z); l.z = f2tf32(v.z - __uint_as_float(h.z));
            h.w = f2tf32(v.w); l.w = f2tf32(v.w - __uint_as_float(h.w));
            *(uint4*)&Bh[kr * BSTR + c4] = h;
            *(uint4*)&Bl[kr * BSTR + c4] = l;
        }
        __syncthreads();

        #pragma unroll
        for (int ks = 0; ks < 4; ks++) {
            uint32_t ah[4][4], bh[4][2], bl[4][2];
            #pragma unroll
            for (int mi = 0; mi < 4; mi++) {
                int base = (wm * 64 + mi * 16 + g) * ASTR + ks * 8 + t;
                ah[mi][0] = Ah[base];
                ah[mi][1] = Ah[base + 8 * ASTR];
                ah[mi][2] = Ah[base + 4];
                ah[mi][3] = Ah[base + 8 * ASTR + 4];
            }
            #pragma unroll
            for (int nj = 0; nj < 4; nj++) {
                int base = (ks * 8 + t) * BSTR + wn * 32 + nj * 8 + g;
                bh[nj][0] = Bh[base];
                bh[nj][1] = Bh[base + 4 * BSTR];
                bl[nj][0] = Bl[base];
                bl[nj][1] = Bl[base + 4 * BSTR];
            }
            #pragma unroll
            for (int mi = 0; mi < 4; mi++)
                #pragma unroll
                for (int nj = 0; nj < 4; nj++) {
                    mma_tf32(acc[mi][nj], ah[mi], bh[nj]);
                    mma_tf32(acc[mi][nj], ah[mi], bl[nj]);
                }
        }
        __syncthreads();
    }

    #pragma unroll
    for (int mi = 0; mi < 4; mi++) {
        #pragma unroll
        for (int nj = 0; nj < 4; nj++) {
            int m0r = bM + wm * 64 + mi * 16 + g;
            int n   = bN + wn * 32 + nj * 8 + t * 2;
            float b0 = bo[n], b1 = bo[n + 1];
            float2 v0 = make_float2(acc[mi][nj][0] + b0, acc[mi][nj][1] + b1);
            float2 v1 = make_float2(acc[mi][nj][2] + b0, acc[mi][nj][3] + b1);
            *(float2*)&outp[(size_t)m0r * EMB + n]       = v0;
            *(float2*)&outp[(size_t)(m0r + 8) * EMB + n] = v1;
        }
    }
}

// ---------------------------------------------------------------------------

extern "C" void kernel_launch(void* const* d_in, const int* in_sizes, int n_in,
                              void* d_out, int out_size)
{
    const float* x  = (const float*)d_in[0];
    const float* Wq = (const float*)d_in[1];
    const float* bq = (const float*)d_in[2];
    const float* Wk = (const float*)d_in[3];
    const float* bk = (const float*)d_in[4];
    const float* Wv = (const float*)d_in[5];
    const float* bv = (const float*)d_in[6];
    const float* Wo = (const float*)d_in[7];
    const float* bo = (const float*)d_in[8];
    float* out = (float*)d_out;

    const int attn_smem = 2 * WG_SMEM;                            // 58368 B
    const int outp_smem = (128 * ASTR + 32 * BSTR * 2) * 4;       // 53248 B
    cudaFuncSetAttribute(attn_kernel,
                         cudaFuncAttributeMaxDynamicSharedMemorySize, attn_smem);
    cudaFuncSetAttribute(out_proj_tf32,
                         cudaFuncAttributeMaxDynamicSharedMemorySize, outp_smem);

    proj_qkv_kernel<<<dim3(EMB / 128, SEQ / 128, 3), 256>>>(x, Wq, bq, Wk, bk, Wv, bv);
    attn_kernel<<<dim3(16, NH), 256, attn_smem>>>();
    out_proj_tf32<<<dim3(EMB / 128, SEQ / 128), 256, outp_smem>>>(Wo, bo, out);
}